// round 2
// baseline (speedup 1.0000x reference)
#include <cuda_runtime.h>
#include <math.h>

// Problem constants
// B=4, S=2048, D=1024, H=16, DK=64  ->  M = B*S = 8192 tokens
// Head split reshape(B*H, S, DK) is an IDENTITY on the flat [B,S,D] buffer:
// attention = 64 independent contiguous [2048,64] problems.
#define MTOK   8192
#define DMODEL 1024
#define BHEADS 64
#define SEQ    2048
#define DKH    64

// ---------------------------------------------------------------------------
// Scratch (device globals: no allocations allowed)
// ---------------------------------------------------------------------------
__device__ float g_qp [MTOK * DMODEL];
__device__ float g_kp [MTOK * DMODEL];
__device__ float g_vp [MTOK * DMODEL];
__device__ float g_ctx[MTOK * DMODEL];

// ---------------------------------------------------------------------------
// GEMM: C[m,n] = sum_k X[m,k] * W[n,k] + bias[n]  (+ optional residual R[m,n])
// X: [M, 1024] row-major, W: [1024, 1024] row-major (torch Linear weight)
// Tiles: BM=BN=128, BK=16; 256 threads; 8x8 per-thread microtile.
// ---------------------------------------------------------------------------
template<bool RES>
__global__ __launch_bounds__(256, 2)
void gemm_nt_kernel(const float* __restrict__ X, const float* __restrict__ W,
                    const float* __restrict__ bias, const float* __restrict__ R,
                    float* __restrict__ C)
{
    const int K = DMODEL;
    __shared__ float Xs[16][132];   // [k][m], padded
    __shared__ float Ws[16][132];   // [k][n], padded

    const int m0  = blockIdx.y * 128;
    const int n0  = blockIdx.x * 128;
    const int tid = threadIdx.x;
    const int tx  = tid & 15;       // n-dir
    const int ty  = tid >> 4;       // m-dir

    float acc[8][8];
#pragma unroll
    for (int i = 0; i < 8; i++)
#pragma unroll
        for (int j = 0; j < 8; j++) acc[i][j] = 0.f;

    for (int k0 = 0; k0 < K; k0 += 16) {
        __syncthreads();
#pragma unroll
        for (int r = 0; r < 2; r++) {
            const int idx = r * 256 + tid;
            const int row = idx >> 2;      // 0..127
            const int c4  = idx & 3;       // 0..3 (float4 within 16-wide k)
            float4 gx = *(const float4*)&X[(size_t)(m0 + row) * K + k0 + c4 * 4];
            Xs[c4 * 4 + 0][row] = gx.x;
            Xs[c4 * 4 + 1][row] = gx.y;
            Xs[c4 * 4 + 2][row] = gx.z;
            Xs[c4 * 4 + 3][row] = gx.w;
            float4 gw = *(const float4*)&W[(size_t)(n0 + row) * K + k0 + c4 * 4];
            Ws[c4 * 4 + 0][row] = gw.x;
            Ws[c4 * 4 + 1][row] = gw.y;
            Ws[c4 * 4 + 2][row] = gw.z;
            Ws[c4 * 4 + 3][row] = gw.w;
        }
        __syncthreads();

#pragma unroll
        for (int kk = 0; kk < 16; kk++) {
            float a[8], b[8];
            *(float4*)&a[0] = *(const float4*)&Xs[kk][ty * 8];
            *(float4*)&a[4] = *(const float4*)&Xs[kk][ty * 8 + 4];
            *(float4*)&b[0] = *(const float4*)&Ws[kk][tx * 8];
            *(float4*)&b[4] = *(const float4*)&Ws[kk][tx * 8 + 4];
#pragma unroll
            for (int i = 0; i < 8; i++)
#pragma unroll
                for (int j = 0; j < 8; j++)
                    acc[i][j] = fmaf(a[i], b[j], acc[i][j]);
        }
    }

    // Epilogue
#pragma unroll
    for (int i = 0; i < 8; i++) {
        const int m = m0 + ty * 8 + i;
#pragma unroll
        for (int j = 0; j < 8; j += 4) {
            const int n = n0 + tx * 8 + j;
            float4 bi = *(const float4*)&bias[n];
            float4 o;
            o.x = acc[i][j + 0] + bi.x;
            o.y = acc[i][j + 1] + bi.y;
            o.z = acc[i][j + 2] + bi.z;
            o.w = acc[i][j + 3] + bi.w;
            if (RES) {
                float4 r4 = *(const float4*)&R[(size_t)m * DMODEL + n];
                o.x += r4.x; o.y += r4.y; o.z += r4.z; o.w += r4.w;
            }
            *(float4*)&C[(size_t)m * DMODEL + n] = o;
        }
    }
}

// ---------------------------------------------------------------------------
// Flash attention over [BH=64][S=2048][DK=64] contiguous buffers.
// Block: (q-tile of 64, bh). 256 threads. Key tiles of 32. Online softmax.
// Thread t: query row qr = t>>2, lane group l4 = t&3.
//   scores: 8 keys (j = l4 + 4k);  ctx: 16 dims (d0 = l4*16).
// ---------------------------------------------------------------------------
__global__ __launch_bounds__(256, 2)
void attn_kernel(const float* __restrict__ Qp, const float* __restrict__ Kp,
                 const float* __restrict__ Vp, float* __restrict__ Ctx)
{
    __shared__ float Qs[64][68];
    __shared__ float Ks[32][68];
    __shared__ float Vs[32][68];
    __shared__ float Ps[64][36];

    const int bh  = blockIdx.y;
    const int q0  = blockIdx.x * 64;
    const int tid = threadIdx.x;
    const int qr  = tid >> 2;
    const int l4  = tid & 3;
    const int d0  = l4 * 16;

    const size_t base = (size_t)bh * SEQ * DKH;

    // Load Q tile [64 x 64], pre-scaled by 1/sqrt(DK) = 0.125
    {
        const float4* Qg = (const float4*)(Qp + base + (size_t)q0 * DKH);
#pragma unroll
        for (int r = 0; r < 4; r++) {
            const int idx = r * 256 + tid;
            const int row = idx >> 4;   // 16 float4 per row
            const int c   = idx & 15;
            float4 v = Qg[row * 16 + c];
            v.x *= 0.125f; v.y *= 0.125f; v.z *= 0.125f; v.w *= 0.125f;
            *(float4*)&Qs[row][c * 4] = v;
        }
    }

    float m_i = -INFINITY, l_i = 0.f;
    float acc[16];
#pragma unroll
    for (int i = 0; i < 16; i++) acc[i] = 0.f;

    for (int kt = 0; kt < SEQ / 32; kt++) {
        __syncthreads();   // prior ctx phase done with Ps/Vs
        {
            const float4* Kg = (const float4*)(Kp + base + (size_t)kt * 32 * DKH);
            const float4* Vg = (const float4*)(Vp + base + (size_t)kt * 32 * DKH);
#pragma unroll
            for (int r = 0; r < 2; r++) {
                const int idx = r * 256 + tid;
                const int row = idx >> 4;
                const int c   = idx & 15;
                *(float4*)&Ks[row][c * 4] = Kg[row * 16 + c];
                *(float4*)&Vs[row][c * 4] = Vg[row * 16 + c];
            }
        }
        __syncthreads();

        // Scores: 8 keys per thread
        float s[8];
#pragma unroll
        for (int k = 0; k < 8; k++) s[k] = 0.f;
#pragma unroll
        for (int d4 = 0; d4 < 16; d4++) {
            float4 q4 = *(const float4*)&Qs[qr][d4 * 4];
#pragma unroll
            for (int k = 0; k < 8; k++) {
                float4 k4 = *(const float4*)&Ks[l4 + 4 * k][d4 * 4];
                s[k] = fmaf(q4.x, k4.x, s[k]);
                s[k] = fmaf(q4.y, k4.y, s[k]);
                s[k] = fmaf(q4.z, k4.z, s[k]);
                s[k] = fmaf(q4.w, k4.w, s[k]);
            }
        }

        // Online softmax over the 4-lane group
        float tm = s[0];
#pragma unroll
        for (int k = 1; k < 8; k++) tm = fmaxf(tm, s[k]);
        tm = fmaxf(tm, __shfl_xor_sync(0xffffffffu, tm, 1));
        tm = fmaxf(tm, __shfl_xor_sync(0xffffffffu, tm, 2));
        const float m_new = fmaxf(m_i, tm);
        const float alpha = __expf(m_i - m_new);

        float psum = 0.f;
#pragma unroll
        for (int k = 0; k < 8; k++) {
            float p = __expf(s[k] - m_new);
            psum += p;
            Ps[qr][l4 + 4 * k] = p;
        }
        psum += __shfl_xor_sync(0xffffffffu, psum, 1);
        psum += __shfl_xor_sync(0xffffffffu, psum, 2);
        l_i = l_i * alpha + psum;
        m_i = m_new;

#pragma unroll
        for (int i = 0; i < 16; i++) acc[i] *= alpha;

        __syncthreads();   // Ps visible

        // ctx += P . V   (16 dims per thread)
#pragma unroll
        for (int j = 0; j < 32; j++) {
            const float p = Ps[qr][j];
#pragma unroll
            for (int c = 0; c < 4; c++) {
                float4 v4 = *(const float4*)&Vs[j][d0 + c * 4];
                acc[c * 4 + 0] = fmaf(p, v4.x, acc[c * 4 + 0]);
                acc[c * 4 + 1] = fmaf(p, v4.y, acc[c * 4 + 1]);
                acc[c * 4 + 2] = fmaf(p, v4.z, acc[c * 4 + 2]);
                acc[c * 4 + 3] = fmaf(p, v4.w, acc[c * 4 + 3]);
            }
        }
    }

    const float inv = 1.f / l_i;
    float4* Og = (float4*)(Ctx + base + (size_t)(q0 + qr) * DKH + d0);
#pragma unroll
    for (int c = 0; c < 4; c++) {
        float4 o;
        o.x = acc[c * 4 + 0] * inv;
        o.y = acc[c * 4 + 1] * inv;
        o.z = acc[c * 4 + 2] * inv;
        o.w = acc[c * 4 + 3] * inv;
        Og[c] = o;
    }
}

// ---------------------------------------------------------------------------
// In-place LayerNorm over last dim (1024). One block (256 thr) per row;
// each thread owns exactly one float4.
// ---------------------------------------------------------------------------
__global__ __launch_bounds__(256)
void layernorm_kernel(float* __restrict__ X, const float* __restrict__ gamma,
                      const float* __restrict__ beta)
{
    __shared__ float rs[8], rss[8];
    const int row = blockIdx.x;
    const int tid = threadIdx.x;

    float4 v = *(const float4*)&X[(size_t)row * DMODEL + tid * 4];
    float s  = v.x + v.y + v.z + v.w;
    float ss = v.x * v.x + v.y * v.y + v.z * v.z + v.w * v.w;

#pragma unroll
    for (int o = 16; o > 0; o >>= 1) {
        s  += __shfl_down_sync(0xffffffffu, s,  o);
        ss += __shfl_down_sync(0xffffffffu, ss, o);
    }
    const int w  = tid >> 5;
    const int ln = tid & 31;
    if (ln == 0) { rs[w] = s; rss[w] = ss; }
    __syncthreads();

    float tot = 0.f, tot2 = 0.f;
#pragma unroll
    for (int i = 0; i < 8; i++) { tot += rs[i]; tot2 += rss[i]; }
    const float mean = tot * (1.f / DMODEL);
    const float var  = tot2 * (1.f / DMODEL) - mean * mean;
    const float rstd = rsqrtf(var + 1e-6f);

    float4 g = *(const float4*)&gamma[tid * 4];
    float4 b = *(const float4*)&beta[tid * 4];
    float4 o;
    o.x = (v.x - mean) * rstd * g.x + b.x;
    o.y = (v.y - mean) * rstd * g.y + b.y;
    o.z = (v.z - mean) * rstd * g.z + b.z;
    o.w = (v.w - mean) * rstd * g.w + b.w;
    *(float4*)&X[(size_t)row * DMODEL + tid * 4] = o;
}

// ---------------------------------------------------------------------------
// Launch
// ---------------------------------------------------------------------------
extern "C" void kernel_launch(void* const* d_in, const int* in_sizes, int n_in,
                              void* d_out, int out_size)
{
    (void)in_sizes; (void)n_in; (void)out_size;
    const float* q     = (const float*)d_in[0];
    const float* k     = (const float*)d_in[1];
    const float* v     = (const float*)d_in[2];
    const float* Wq    = (const float*)d_in[3];
    const float* bq    = (const float*)d_in[4];
    const float* Wk    = (const float*)d_in[5];
    const float* bk    = (const float*)d_in[6];
    const float* Wv    = (const float*)d_in[7];
    const float* bv    = (const float*)d_in[8];
    const float* Wo    = (const float*)d_in[9];
    const float* bo    = (const float*)d_in[10];
    const float* gamma = (const float*)d_in[11];
    const float* beta  = (const float*)d_in[12];
    float* out = (float*)d_out;

    float *qp, *kp, *vp, *ctx;
    cudaGetSymbolAddress((void**)&qp,  g_qp);
    cudaGetSymbolAddress((void**)&kp,  g_kp);
    cudaGetSymbolAddress((void**)&vp,  g_vp);
    cudaGetSymbolAddress((void**)&ctx, g_ctx);

    dim3 gGemm(DMODEL / 128, MTOK / 128);   // (8, 64)
    gemm_nt_kernel<false><<<gGemm, 256>>>(q, Wq, bq, nullptr, qp);
    gemm_nt_kernel<false><<<gGemm, 256>>>(k, Wk, bk, nullptr, kp);
    gemm_nt_kernel<false><<<gGemm, 256>>>(v, Wv, bv, nullptr, vp);

    dim3 gAttn(SEQ / 64, BHEADS);           // (32, 64)
    attn_kernel<<<gAttn, 256>>>(qp, kp, vp, ctx);

    // out = residual(q) + ctx @ Wo^T + bo
    gemm_nt_kernel<true><<<gGemm, 256>>>(ctx, Wo, bo, q, out);

    layernorm_kernel<<<MTOK, 256>>>(out, gamma, beta);
}

// round 5
// speedup vs baseline: 6.9561x; 6.9561x over previous
#include <cuda_runtime.h>
#include <math.h>
#include <stdint.h>

// B=4, S=2048, D=1024, H=16, DK=64 -> M = 8192 tokens.
// Head split reshape(B*H, S, DK) is an identity on the flat buffer:
// attention = 64 independent contiguous [2048,64] problems.
#define MTOK   8192
#define DMODEL 1024
#define BHEADS 64
#define SEQ    2048
#define DKH    64

// Scratch (device globals: no allocations allowed)
__device__ float g_qp [MTOK * DMODEL];
__device__ float g_kp [MTOK * DMODEL];
__device__ float g_vp [MTOK * DMODEL];
__device__ float g_ctx[MTOK * DMODEL];

// ---------------------------------------------------------------------------
// PTX helpers
// ---------------------------------------------------------------------------
__device__ __forceinline__ uint32_t f2tf32(float f) {
    uint32_t u;
    asm("cvt.rna.tf32.f32 %0, %1;" : "=r"(u) : "f"(f));
    return u;
}

__device__ __forceinline__ void ldsm4(uint32_t* r, uint32_t saddr) {
    asm volatile("ldmatrix.sync.aligned.m8n8.x4.shared.b16 {%0,%1,%2,%3}, [%4];"
                 : "=r"(r[0]), "=r"(r[1]), "=r"(r[2]), "=r"(r[3]) : "r"(saddr));
}

__device__ __forceinline__ void mma_tf32(float* c, const uint32_t* a, const uint32_t* b) {
    asm volatile(
        "mma.sync.aligned.m16n8k8.row.col.f32.tf32.tf32.f32 "
        "{%0,%1,%2,%3}, {%4,%5,%6,%7}, {%8,%9}, {%0,%1,%2,%3};"
        : "+f"(c[0]), "+f"(c[1]), "+f"(c[2]), "+f"(c[3])
        : "r"(a[0]), "r"(a[1]), "r"(a[2]), "r"(a[3]), "r"(b[0]), "r"(b[1]));
}

// ---------------------------------------------------------------------------
// TF32 GEMM: C[m,n] = sum_k X[m,k]*W[n,k] + bias[n] (+ optional residual)
// Block 128x128, BK=32, 8 warps; warp tile 64(m) x 32(n).
// SMEM stride 36 words (36 mod 32 == 4 -> conflict-free ldmatrix).
// ---------------------------------------------------------------------------
template<bool RES>
__global__ __launch_bounds__(256, 2)
void gemm_tf32(const float* __restrict__ X, const float* __restrict__ W,
               const float* __restrict__ bias, const float* __restrict__ R,
               float* __restrict__ C)
{
    __shared__ uint32_t Xs[128 * 36];
    __shared__ uint32_t Ws[128 * 36];

    const int tid  = threadIdx.x;
    const int lane = tid & 31;
    const int wid  = tid >> 5;
    const int m0   = blockIdx.y * 128;
    const int n0   = blockIdx.x * 128;
    const int wm   = (wid & 1) * 64;       // warp m offset (4 m16 tiles)
    const int wn   = (wid >> 1) * 32;      // warp n offset (4 n8 tiles)

    float acc[4][4][4];
#pragma unroll
    for (int i = 0; i < 4; i++)
#pragma unroll
        for (int j = 0; j < 4; j++)
#pragma unroll
            for (int c = 0; c < 4; c++) acc[i][j][c] = 0.f;

    const uint32_t xs_base = (uint32_t)__cvta_generic_to_shared(Xs);
    const uint32_t ws_base = (uint32_t)__cvta_generic_to_shared(Ws);

    // ldmatrix thread address components
    const int a_row = wm + (lane & 7) + 8 * ((lane >> 3) & 1);
    const int a_col = 4 * (lane >> 4);
    const int b_row = wn + (lane & 7) + 8 * (lane >> 4);
    const int b_col = 4 * ((lane >> 3) & 1);

    for (int k0 = 0; k0 < DMODEL; k0 += 32) {
        __syncthreads();
#pragma unroll
        for (int it = 0; it < 4; it++) {
            const int idx = it * 256 + tid;
            const int row = idx >> 3;
            const int c4  = (idx & 7) * 4;
            float4 gx = *(const float4*)&X[(size_t)(m0 + row) * DMODEL + k0 + c4];
            uint4 ux; ux.x = f2tf32(gx.x); ux.y = f2tf32(gx.y);
                      ux.z = f2tf32(gx.z); ux.w = f2tf32(gx.w);
            *(uint4*)&Xs[row * 36 + c4] = ux;
            float4 gw = *(const float4*)&W[(size_t)(n0 + row) * DMODEL + k0 + c4];
            uint4 uw; uw.x = f2tf32(gw.x); uw.y = f2tf32(gw.y);
                      uw.z = f2tf32(gw.z); uw.w = f2tf32(gw.w);
            *(uint4*)&Ws[row * 36 + c4] = uw;
        }
        __syncthreads();

#pragma unroll
        for (int kk = 0; kk < 32; kk += 8) {
            uint32_t A[4][4], Bf[2][4];
#pragma unroll
            for (int i = 0; i < 4; i++)
                ldsm4(A[i], xs_base + (uint32_t)(((a_row + 16 * i) * 36 + kk + a_col) * 4));
#pragma unroll
            for (int jj = 0; jj < 2; jj++)
                ldsm4(Bf[jj], ws_base + (uint32_t)(((b_row + 16 * jj) * 36 + kk + b_col) * 4));
#pragma unroll
            for (int i = 0; i < 4; i++)
#pragma unroll
                for (int j = 0; j < 4; j++)
                    mma_tf32(acc[i][j], A[i], &Bf[j >> 1][(j & 1) * 2]);
        }
    }

    // Epilogue: c0,c1 -> (row g, cols 2q,2q+1); c2,c3 -> row g+8
    const int q = lane & 3, g = lane >> 2;
#pragma unroll
    for (int i = 0; i < 4; i++) {
#pragma unroll
        for (int j = 0; j < 4; j++) {
            const int row0 = m0 + wm + 16 * i + g;
            const int col  = n0 + wn + 8 * j + 2 * q;
            float2 bi = *(const float2*)&bias[col];
            float2 o0, o1;
            o0.x = acc[i][j][0] + bi.x; o0.y = acc[i][j][1] + bi.y;
            o1.x = acc[i][j][2] + bi.x; o1.y = acc[i][j][3] + bi.y;
            if (RES) {
                float2 r0 = *(const float2*)&R[(size_t)row0 * DMODEL + col];
                float2 r1 = *(const float2*)&R[(size_t)(row0 + 8) * DMODEL + col];
                o0.x += r0.x; o0.y += r0.y;
                o1.x += r1.x; o1.y += r1.y;
            }
            *(float2*)&C[(size_t)row0 * DMODEL + col]       = o0;
            *(float2*)&C[(size_t)(row0 + 8) * DMODEL + col] = o1;
        }
    }
}

// ---------------------------------------------------------------------------
// TF32 flash attention. Block: q-tile 128 x key-tiles of 64, 8 warps;
// warp owns 16 q rows. Strides: Qs/Ks/Ps 68 (ldmatrix conflict-free),
// Vs 72 (lds.32 B-frag conflict-free).
// ---------------------------------------------------------------------------
__global__ __launch_bounds__(256)
void attn_tf32(const float* __restrict__ Qp, const float* __restrict__ Kp,
               const float* __restrict__ Vp, float* __restrict__ Ctx)
{
    extern __shared__ uint32_t sm[];
    uint32_t* Qs = sm;                        // 128*68
    uint32_t* Ks = Qs + 128 * 68;             // 64*68
    uint32_t* Vs = Ks + 64 * 68;              // 64*72
    uint32_t* Ps = Vs + 64 * 72;              // 128*68

    const int tid  = threadIdx.x;
    const int lane = tid & 31;
    const int wid  = tid >> 5;
    const int bh   = blockIdx.y;
    const int q0   = blockIdx.x * 128;
    const size_t base = (size_t)bh * SEQ * DKH;

    const int q = lane & 3, g = lane >> 2;
    const int lrow  = (lane & 7) + 8 * ((lane >> 3) & 1);  // A-type ldsm rows
    const int lcolA = 4 * (lane >> 4);
    const int browK = (lane & 7) + 8 * (lane >> 4);        // B-type ldsm rows
    const int bcolK = 4 * ((lane >> 3) & 1);

    const uint32_t qs_base = (uint32_t)__cvta_generic_to_shared(Qs);
    const uint32_t ks_base = (uint32_t)__cvta_generic_to_shared(Ks);
    const uint32_t ps_base = (uint32_t)__cvta_generic_to_shared(Ps);

    // Stage Q (pre-scaled by 1/8)
    {
        const float* Qg = Qp + base + (size_t)q0 * DKH;
#pragma unroll
        for (int it = 0; it < 8; it++) {
            const int idx = it * 256 + tid;
            const int row = idx >> 4;
            const int c4  = (idx & 15) * 4;
            float4 v = *(const float4*)&Qg[(size_t)row * DKH + c4];
            uint4 u; u.x = f2tf32(v.x * 0.125f); u.y = f2tf32(v.y * 0.125f);
                     u.z = f2tf32(v.z * 0.125f); u.w = f2tf32(v.w * 0.125f);
            *(uint4*)&Qs[row * 68 + c4] = u;
        }
    }

    float m0r = -INFINITY, m1r = -INFINITY, l0 = 0.f, l1 = 0.f;
    float o[8][4];
#pragma unroll
    for (int j = 0; j < 8; j++)
#pragma unroll
        for (int c = 0; c < 4; c++) o[j][c] = 0.f;

    for (int kt = 0; kt < SEQ / 64; kt++) {
        __syncthreads();   // prior iteration done with Ks/Vs (also covers Q staging)
        {
            const float* Kg = Kp + base + (size_t)(kt * 64) * DKH;
            const float* Vg = Vp + base + (size_t)(kt * 64) * DKH;
#pragma unroll
            for (int it = 0; it < 4; it++) {
                const int idx = it * 256 + tid;
                const int row = idx >> 4;
                const int c4  = (idx & 15) * 4;
                float4 kv = *(const float4*)&Kg[(size_t)row * DKH + c4];
                uint4 uk; uk.x = f2tf32(kv.x); uk.y = f2tf32(kv.y);
                          uk.z = f2tf32(kv.z); uk.w = f2tf32(kv.w);
                *(uint4*)&Ks[row * 68 + c4] = uk;
                float4 vv = *(const float4*)&Vg[(size_t)row * DKH + c4];
                uint4 uv; uv.x = f2tf32(vv.x); uv.y = f2tf32(vv.y);
                          uv.z = f2tf32(vv.z); uv.w = f2tf32(vv.w);
                *(uint4*)&Vs[row * 72 + c4] = uv;
            }
        }
        __syncthreads();

        // --- Scores: S[16 x 64] per warp ---
        float s[8][4];
#pragma unroll
        for (int j = 0; j < 8; j++)
#pragma unroll
            for (int c = 0; c < 4; c++) s[j][c] = 0.f;

#pragma unroll
        for (int kk = 0; kk < 64; kk += 8) {
            uint32_t A[4];
            ldsm4(A, qs_base + (uint32_t)(((16 * wid + lrow) * 68 + kk + lcolA) * 4));
            uint32_t Bf[4][4];
#pragma unroll
            for (int jj = 0; jj < 4; jj++)
                ldsm4(Bf[jj], ks_base + (uint32_t)(((16 * jj + browK) * 68 + kk + bcolK) * 4));
#pragma unroll
            for (int j = 0; j < 8; j++)
                mma_tf32(s[j], A, &Bf[j >> 1][(j & 1) * 2]);
        }

        // --- Online softmax (rows r0 = 16*wid+g, r1 = r0+8) ---
        float mx0 = s[0][0], mx1 = s[0][2];
#pragma unroll
        for (int j = 0; j < 8; j++) {
            mx0 = fmaxf(mx0, fmaxf(s[j][0], s[j][1]));
            mx1 = fmaxf(mx1, fmaxf(s[j][2], s[j][3]));
        }
        mx0 = fmaxf(mx0, __shfl_xor_sync(0xffffffffu, mx0, 1));
        mx0 = fmaxf(mx0, __shfl_xor_sync(0xffffffffu, mx0, 2));
        mx1 = fmaxf(mx1, __shfl_xor_sync(0xffffffffu, mx1, 1));
        mx1 = fmaxf(mx1, __shfl_xor_sync(0xffffffffu, mx1, 2));
        const float mn0 = fmaxf(m0r, mx0), mn1 = fmaxf(m1r, mx1);
        const float al0 = __expf(m0r - mn0), al1 = __expf(m1r - mn1);

        float sum0 = 0.f, sum1 = 0.f;
        const int pr0 = (16 * wid + g) * 68;
        const int pr1 = (16 * wid + g + 8) * 68;
#pragma unroll
        for (int j = 0; j < 8; j++) {
            const float p0 = __expf(s[j][0] - mn0);
            const float p1 = __expf(s[j][1] - mn0);
            const float p2 = __expf(s[j][2] - mn1);
            const float p3 = __expf(s[j][3] - mn1);
            sum0 += p0 + p1;
            sum1 += p2 + p3;
            uint2 u0; u0.x = f2tf32(p0); u0.y = f2tf32(p1);
            uint2 u1; u1.x = f2tf32(p2); u1.y = f2tf32(p3);
            *(uint2*)&Ps[pr0 + 8 * j + 2 * q] = u0;
            *(uint2*)&Ps[pr1 + 8 * j + 2 * q] = u1;
        }
        sum0 += __shfl_xor_sync(0xffffffffu, sum0, 1);
        sum0 += __shfl_xor_sync(0xffffffffu, sum0, 2);
        sum1 += __shfl_xor_sync(0xffffffffu, sum1, 1);
        sum1 += __shfl_xor_sync(0xffffffffu, sum1, 2);
        l0 = l0 * al0 + sum0;
        l1 = l1 * al1 + sum1;
        m0r = mn0; m1r = mn1;

#pragma unroll
        for (int j = 0; j < 8; j++) {
            o[j][0] *= al0; o[j][1] *= al0;
            o[j][2] *= al1; o[j][3] *= al1;
        }
        __syncwarp();   // own-warp P visible for ldmatrix

        // --- ctx += P · V ---
#pragma unroll
        for (int kk = 0; kk < 64; kk += 8) {
            uint32_t A[4];
            ldsm4(A, ps_base + (uint32_t)(((16 * wid + lrow) * 68 + kk + lcolA) * 4));
#pragma unroll
            for (int j = 0; j < 8; j++) {
                uint32_t b[2];
                b[0] = Vs[(kk + q) * 72 + 8 * j + g];
                b[1] = Vs[(kk + 4 + q) * 72 + 8 * j + g];
                mma_tf32(o[j], A, b);
            }
        }
    }

    // Epilogue: normalize and store
    const float inv0 = 1.f / l0, inv1 = 1.f / l1;
    const int row0 = q0 + 16 * wid + g;
#pragma unroll
    for (int j = 0; j < 8; j++) {
        float2 a, b2;
        a.x  = o[j][0] * inv0; a.y  = o[j][1] * inv0;
        b2.x = o[j][2] * inv1; b2.y = o[j][3] * inv1;
        *(float2*)&Ctx[base + (size_t)row0 * DKH + 8 * j + 2 * q]       = a;
        *(float2*)&Ctx[base + (size_t)(row0 + 8) * DKH + 8 * j + 2 * q] = b2;
    }
}

// ---------------------------------------------------------------------------
// In-place LayerNorm over last dim (1024). One block (256 thr) per row.
// ---------------------------------------------------------------------------
__global__ __launch_bounds__(256)
void layernorm_kernel(float* __restrict__ X, const float* __restrict__ gamma,
                      const float* __restrict__ beta)
{
    __shared__ float rs[8], rss[8];
    const int row = blockIdx.x;
    const int tid = threadIdx.x;

    float4 v = *(const float4*)&X[(size_t)row * DMODEL + tid * 4];
    float s  = v.x + v.y + v.z + v.w;
    float ss = v.x * v.x + v.y * v.y + v.z * v.z + v.w * v.w;

#pragma unroll
    for (int o = 16; o > 0; o >>= 1) {
        s  += __shfl_down_sync(0xffffffffu, s,  o);
        ss += __shfl_down_sync(0xffffffffu, ss, o);
    }
    const int w  = tid >> 5;
    const int ln = tid & 31;
    if (ln == 0) { rs[w] = s; rss[w] = ss; }
    __syncthreads();

    float tot = 0.f, tot2 = 0.f;
#pragma unroll
    for (int i = 0; i < 8; i++) { tot += rs[i]; tot2 += rss[i]; }
    const float mean = tot * (1.f / DMODEL);
    const float var  = tot2 * (1.f / DMODEL) - mean * mean;
    const float rstd = rsqrtf(var + 1e-6f);

    float4 g4 = *(const float4*)&gamma[tid * 4];
    float4 b4 = *(const float4*)&beta[tid * 4];
    float4 o;
    o.x = (v.x - mean) * rstd * g4.x + b4.x;
    o.y = (v.y - mean) * rstd * g4.y + b4.y;
    o.z = (v.z - mean) * rstd * g4.z + b4.z;
    o.w = (v.w - mean) * rstd * g4.w + b4.w;
    *(float4*)&X[(size_t)row * DMODEL + tid * 4] = o;
}

// ---------------------------------------------------------------------------
// Launch
// ---------------------------------------------------------------------------
extern "C" void kernel_launch(void* const* d_in, const int* in_sizes, int n_in,
                              void* d_out, int out_size)
{
    (void)in_sizes; (void)n_in; (void)out_size;
    const float* q     = (const float*)d_in[0];
    const float* k     = (const float*)d_in[1];
    const float* v     = (const float*)d_in[2];
    const float* Wq    = (const float*)d_in[3];
    const float* bq    = (const float*)d_in[4];
    const float* Wk    = (const float*)d_in[5];
    const float* bk    = (const float*)d_in[6];
    const float* Wv    = (const float*)d_in[7];
    const float* bv    = (const float*)d_in[8];
    const float* Wo    = (const float*)d_in[9];
    const float* bo    = (const float*)d_in[10];
    const float* gamma = (const float*)d_in[11];
    const float* beta  = (const float*)d_in[12];
    float* out = (float*)d_out;

    float *qp, *kp, *vp, *ctx;
    cudaGetSymbolAddress((void**)&qp,  g_qp);
    cudaGetSymbolAddress((void**)&kp,  g_kp);
    cudaGetSymbolAddress((void**)&vp,  g_vp);
    cudaGetSymbolAddress((void**)&ctx, g_ctx);

    static int attn_smem_set = 0;
    const int attn_smem = (128 * 68 + 64 * 68 + 64 * 72 + 128 * 68) * 4;
    if (!attn_smem_set) {
        cudaFuncSetAttribute(attn_tf32, cudaFuncAttributeMaxDynamicSharedMemorySize, attn_smem);
        attn_smem_set = 1;
    }

    dim3 gGemm(DMODEL / 128, MTOK / 128);   // (8, 64)
    gemm_tf32<false><<<gGemm, 256>>>(q, Wq, bq, nullptr, qp);
    gemm_tf32<false><<<gGemm, 256>>>(k, Wk, bk, nullptr, kp);
    gemm_tf32<false><<<gGemm, 256>>>(v, Wv, bv, nullptr, vp);

    dim3 gAttn(SEQ / 128, BHEADS);          // (16, 64)
    attn_tf32<<<gAttn, 256, attn_smem>>>(qp, kp, vp, ctx);

    gemm_tf32<true><<<gGemm, 256>>>(ctx, Wo, bo, q, out);

    layernorm_kernel<<<MTOK, 256>>>(out, gamma, beta);
}

// round 11
// speedup vs baseline: 11.9107x; 1.7123x over previous
#include <cuda_runtime.h>
#include <cuda_bf16.h>
#include <math.h>
#include <stdint.h>

// B=4, S=2048, D=1024, H=16, DK=64 -> M = 8192 tokens.
// Head split reshape(B*H, S, DK) is an identity on the flat buffer:
// attention = 64 independent contiguous [2048,64] problems.
#define MTOK   8192
#define DMODEL 1024
#define BHEADS 64
#define SEQ    2048
#define DKH    64

// Scratch (device globals: no allocations allowed)
__device__ float g_qp [MTOK * DMODEL];
__device__ float g_kp [MTOK * DMODEL];
__device__ float g_vp [MTOK * DMODEL];
__device__ float g_ctx[MTOK * DMODEL];

// ---------------------------------------------------------------------------
// PTX helpers
// ---------------------------------------------------------------------------
__device__ __forceinline__ uint32_t packbf(float lo, float hi) {
    uint32_t r;
    asm("cvt.rn.bf16x2.f32 %0, %1, %2;" : "=r"(r) : "f"(hi), "f"(lo));
    return r;
}

__device__ __forceinline__ void ldsm4(uint32_t* r, uint32_t saddr) {
    asm volatile("ldmatrix.sync.aligned.m8n8.x4.shared.b16 {%0,%1,%2,%3}, [%4];"
                 : "=r"(r[0]), "=r"(r[1]), "=r"(r[2]), "=r"(r[3]) : "r"(saddr));
}

__device__ __forceinline__ void ldsm4t(uint32_t* r, uint32_t saddr) {
    asm volatile("ldmatrix.sync.aligned.m8n8.x4.trans.shared.b16 {%0,%1,%2,%3}, [%4];"
                 : "=r"(r[0]), "=r"(r[1]), "=r"(r[2]), "=r"(r[3]) : "r"(saddr));
}

__device__ __forceinline__ void mma_bf16(float* c, const uint32_t* a, const uint32_t* b) {
    asm volatile(
        "mma.sync.aligned.m16n8k16.row.col.f32.bf16.bf16.f32 "
        "{%0,%1,%2,%3}, {%4,%5,%6,%7}, {%8,%9}, {%0,%1,%2,%3};"
        : "+f"(c[0]), "+f"(c[1]), "+f"(c[2]), "+f"(c[3])
        : "r"(a[0]), "r"(a[1]), "r"(a[2]), "r"(a[3]), "r"(b[0]), "r"(b[1]));
}

// ---------------------------------------------------------------------------
// BF16 GEMM body: C[m,n] = sum_k X[m,k]*W[n,k] + bias[n] (+ optional residual)
// Block 128x128, BK=32, 8 warps; warp tile 64(m) x 32(n). m16n8k16 MMA.
// SMEM row stride 40 bf16 (80 B) -> conflict-free ldmatrix.
// Register-prefetch double buffering.
// ---------------------------------------------------------------------------
template<bool RES>
__device__ __forceinline__
void gemm_body(const float* __restrict__ X, const float* __restrict__ W,
               const float* __restrict__ bias, const float* __restrict__ R,
               float* __restrict__ C, int m0, int n0)
{
    __shared__ __nv_bfloat16 Xs[2][128 * 40];
    __shared__ __nv_bfloat16 Ws[2][128 * 40];

    const int tid  = threadIdx.x;
    const int lane = tid & 31;
    const int wid  = tid >> 5;
    const int wm   = (wid & 1) * 64;
    const int wn   = (wid >> 1) * 32;

    float acc[4][4][4];
#pragma unroll
    for (int i = 0; i < 4; i++)
#pragma unroll
        for (int j = 0; j < 4; j++)
#pragma unroll
            for (int c = 0; c < 4; c++) acc[i][j][c] = 0.f;

    // Staging: row = tid>>3 (+32/it), col = (tid&7)*4
    const int s_row = tid >> 3;
    const int s_col = (tid & 7) * 4;

    uint2 px[4], pw[4];
#define GEMM_LOAD(K0)                                                          \
    {                                                                          \
        _Pragma("unroll")                                                      \
        for (int it = 0; it < 4; it++) {                                       \
            const int row = s_row + it * 32;                                   \
            float4 gx = *(const float4*)&X[(size_t)(m0 + row) * DMODEL + (K0) + s_col]; \
            px[it].x = packbf(gx.x, gx.y); px[it].y = packbf(gx.z, gx.w);      \
            float4 gw = *(const float4*)&W[(size_t)(n0 + row) * DMODEL + (K0) + s_col]; \
            pw[it].x = packbf(gw.x, gw.y); pw[it].y = packbf(gw.z, gw.w);      \
        }                                                                      \
    }
#define GEMM_STORE(BUF)                                                        \
    {                                                                          \
        _Pragma("unroll")                                                      \
        for (int it = 0; it < 4; it++) {                                       \
            const int row = s_row + it * 32;                                   \
            *(uint2*)&Xs[BUF][row * 40 + s_col] = px[it];                      \
            *(uint2*)&Ws[BUF][row * 40 + s_col] = pw[it];                      \
        }                                                                      \
    }

    // ldmatrix address components (byte offsets within a row are 2*col)
    const int a_row = wm + (lane & 15);                 // + 16*i
    const int a_byt = 16 * (lane >> 4);                 // + 2*kk
    const int b_row = wn + 8 * (lane >> 4) + (lane & 7);// + 16*tp
    const int b_byt = 16 * ((lane >> 3) & 1);           // + 2*kk

    GEMM_LOAD(0);
    GEMM_STORE(0);
    __syncthreads();

    for (int s = 1; s <= DMODEL / 32; s++) {
        if (s < DMODEL / 32) GEMM_LOAD(s * 32);

        const int buf = (s - 1) & 1;
        const uint32_t xb = (uint32_t)__cvta_generic_to_shared(&Xs[buf][0]);
        const uint32_t wb = (uint32_t)__cvta_generic_to_shared(&Ws[buf][0]);
#pragma unroll
        for (int kk = 0; kk < 32; kk += 16) {
            uint32_t A[4][4], Bf[2][4];
#pragma unroll
            for (int i = 0; i < 4; i++)
                ldsm4(A[i], xb + (uint32_t)((a_row + 16 * i) * 80 + 2 * kk + a_byt));
#pragma unroll
            for (int tp = 0; tp < 2; tp++)
                ldsm4(Bf[tp], wb + (uint32_t)((b_row + 16 * tp) * 80 + 2 * kk + b_byt));
#pragma unroll
            for (int i = 0; i < 4; i++)
#pragma unroll
                for (int j = 0; j < 4; j++)
                    mma_bf16(acc[i][j], A[i], &Bf[j >> 1][(j & 1) * 2]);
        }

        if (s < DMODEL / 32) GEMM_STORE(s & 1);
        __syncthreads();
    }

    // Epilogue
    const int q = lane & 3, g = lane >> 2;
#pragma unroll
    for (int i = 0; i < 4; i++) {
#pragma unroll
        for (int j = 0; j < 4; j++) {
            const int row0 = m0 + wm + 16 * i + g;
            const int col  = n0 + wn + 8 * j + 2 * q;
            float2 bi = *(const float2*)&bias[col];
            float2 o0, o1;
            o0.x = acc[i][j][0] + bi.x; o0.y = acc[i][j][1] + bi.y;
            o1.x = acc[i][j][2] + bi.x; o1.y = acc[i][j][3] + bi.y;
            if (RES) {
                float2 r0 = *(const float2*)&R[(size_t)row0 * DMODEL + col];
                float2 r1 = *(const float2*)&R[(size_t)(row0 + 8) * DMODEL + col];
                o0.x += r0.x; o0.y += r0.y;
                o1.x += r1.x; o1.y += r1.y;
            }
            *(float2*)&C[(size_t)row0 * DMODEL + col]       = o0;
            *(float2*)&C[(size_t)(row0 + 8) * DMODEL + col] = o1;
        }
    }
#undef GEMM_LOAD
#undef GEMM_STORE
}

// Batched QKV projection: blockIdx.z selects (X, W, b, C) triple.
__global__ __launch_bounds__(256, 2)
void gemm_qkv_bf16(const float* __restrict__ xq, const float* __restrict__ xk,
                   const float* __restrict__ xv,
                   const float* __restrict__ Wq, const float* __restrict__ Wk,
                   const float* __restrict__ Wv,
                   const float* __restrict__ bq, const float* __restrict__ bk,
                   const float* __restrict__ bv,
                   float* __restrict__ qp, float* __restrict__ kp,
                   float* __restrict__ vp)
{
    const float *X, *W, *b;
    float* C;
    if (blockIdx.z == 0)      { X = xq; W = Wq; b = bq; C = qp; }
    else if (blockIdx.z == 1) { X = xk; W = Wk; b = bk; C = kp; }
    else                      { X = xv; W = Wv; b = bv; C = vp; }
    gemm_body<false>(X, W, b, nullptr, C, blockIdx.y * 128, blockIdx.x * 128);
}

// O projection with residual add.
__global__ __launch_bounds__(256, 2)
void gemm_o_bf16(const float* __restrict__ X, const float* __restrict__ W,
                 const float* __restrict__ bias, const float* __restrict__ R,
                 float* __restrict__ C)
{
    gemm_body<true>(X, W, bias, R, C, blockIdx.y * 128, blockIdx.x * 128);
}

// ---------------------------------------------------------------------------
// BF16 flash attention. Block: q-tile 128, key tiles of 64, 8 warps
// (16 q rows each). m16n8k16 MMA. P stays in registers (accumulator
// fragment repacks directly into the PV A fragment). V B-fragments via
// ldmatrix.trans on row-major V. SMEM row stride 72 bf16 (144 B).
// ---------------------------------------------------------------------------
__global__ __launch_bounds__(256)
void attn_bf16(const float* __restrict__ Qp, const float* __restrict__ Kp,
               const float* __restrict__ Vp, float* __restrict__ Ctx)
{
    __shared__ __nv_bfloat16 Qs[128 * 72];
    __shared__ __nv_bfloat16 Ks[64 * 72];
    __shared__ __nv_bfloat16 Vs[64 * 72];

    const int tid  = threadIdx.x;
    const int lane = tid & 31;
    const int wid  = tid >> 5;
    const int bh   = blockIdx.y;
    const int q0   = blockIdx.x * 128;
    const size_t base = (size_t)bh * SEQ * DKH;

    const int q = lane & 3, g = lane >> 2;

    // ldmatrix address components
    const int a_row = 16 * wid + (lane & 15);            // Q rows (A frags)
    const int a_byt = 16 * (lane >> 4);
    const int k_row = 8 * (lane >> 4) + (lane & 7);      // K rows (B frags), +16*tp
    const int k_byt = 16 * ((lane >> 3) & 1);
    const int v_row = 8 * ((lane >> 3) & 1) + (lane & 7);// V rows (trans B frags), +16*kc
    const int v_byt = 16 * (lane >> 4);                  // +32*jp

    const uint32_t qs_b = (uint32_t)__cvta_generic_to_shared(Qs);
    const uint32_t ks_b = (uint32_t)__cvta_generic_to_shared(Ks);
    const uint32_t vs_b = (uint32_t)__cvta_generic_to_shared(Vs);

    // Stage Q (pre-scaled by 1/8): 128x64 fp32 -> bf16
    {
        const float* Qg = Qp + base + (size_t)q0 * DKH;
        const int row = tid >> 4;            // +16 per it
        const int c4  = (tid & 15) * 4;
#pragma unroll
        for (int it = 0; it < 8; it++) {
            const int r = row + it * 16;
            float4 v = *(const float4*)&Qg[(size_t)r * DKH + c4];
            uint2 u; u.x = packbf(v.x * 0.125f, v.y * 0.125f);
                     u.y = packbf(v.z * 0.125f, v.w * 0.125f);
            *(uint2*)&Qs[r * 72 + c4] = u;
        }
    }

    float m0r = -INFINITY, m1r = -INFINITY, l0 = 0.f, l1 = 0.f;
    float o[8][4];
#pragma unroll
    for (int j = 0; j < 8; j++)
#pragma unroll
        for (int c = 0; c < 4; c++) o[j][c] = 0.f;

    for (int kt = 0; kt < SEQ / 64; kt++) {
        __syncthreads();   // prior iteration done with Ks/Vs (covers Q staging too)
        {
            const float* Kg = Kp + base + (size_t)(kt * 64) * DKH;
            const float* Vg = Vp + base + (size_t)(kt * 64) * DKH;
            const int row = tid >> 4;
            const int c4  = (tid & 15) * 4;
#pragma unroll
            for (int it = 0; it < 4; it++) {
                const int r = row + it * 16;
                float4 kv = *(const float4*)&Kg[(size_t)r * DKH + c4];
                uint2 uk; uk.x = packbf(kv.x, kv.y); uk.y = packbf(kv.z, kv.w);
                *(uint2*)&Ks[r * 72 + c4] = uk;
                float4 vv = *(const float4*)&Vg[(size_t)r * DKH + c4];
                uint2 uv; uv.x = packbf(vv.x, vv.y); uv.y = packbf(vv.z, vv.w);
                *(uint2*)&Vs[r * 72 + c4] = uv;
            }
        }
        __syncthreads();

        // --- Scores: S[16 x 64] per warp ---
        float s[8][4];
#pragma unroll
        for (int j = 0; j < 8; j++)
#pragma unroll
            for (int c = 0; c < 4; c++) s[j][c] = 0.f;

#pragma unroll
        for (int kk = 0; kk < 64; kk += 16) {
            uint32_t A[4], Bf[4][4];
            ldsm4(A, qs_b + (uint32_t)(a_row * 144 + 2 * kk + a_byt));
#pragma unroll
            for (int tp = 0; tp < 4; tp++)
                ldsm4(Bf[tp], ks_b + (uint32_t)((k_row + 16 * tp) * 144 + 2 * kk + k_byt));
#pragma unroll
            for (int j = 0; j < 8; j++)
                mma_bf16(s[j], A, &Bf[j >> 1][(j & 1) * 2]);
        }

        // --- Online softmax (rows r0 = 16*wid+g, r1 = r0+8) ---
        float mx0 = s[0][0], mx1 = s[0][2];
#pragma unroll
        for (int j = 0; j < 8; j++) {
            mx0 = fmaxf(mx0, fmaxf(s[j][0], s[j][1]));
            mx1 = fmaxf(mx1, fmaxf(s[j][2], s[j][3]));
        }
        mx0 = fmaxf(mx0, __shfl_xor_sync(0xffffffffu, mx0, 1));
        mx0 = fmaxf(mx0, __shfl_xor_sync(0xffffffffu, mx0, 2));
        mx1 = fmaxf(mx1, __shfl_xor_sync(0xffffffffu, mx1, 1));
        mx1 = fmaxf(mx1, __shfl_xor_sync(0xffffffffu, mx1, 2));
        const float mn0 = fmaxf(m0r, mx0), mn1 = fmaxf(m1r, mx1);
        const float al0 = __expf(m0r - mn0), al1 = __expf(m1r - mn1);

        float sum0 = 0.f, sum1 = 0.f;
#pragma unroll
        for (int j = 0; j < 8; j++) {
            s[j][0] = __expf(s[j][0] - mn0);
            s[j][1] = __expf(s[j][1] - mn0);
            s[j][2] = __expf(s[j][2] - mn1);
            s[j][3] = __expf(s[j][3] - mn1);
            sum0 += s[j][0] + s[j][1];
            sum1 += s[j][2] + s[j][3];
        }
        sum0 += __shfl_xor_sync(0xffffffffu, sum0, 1);
        sum0 += __shfl_xor_sync(0xffffffffu, sum0, 2);
        sum1 += __shfl_xor_sync(0xffffffffu, sum1, 1);
        sum1 += __shfl_xor_sync(0xffffffffu, sum1, 2);
        l0 = l0 * al0 + sum0;
        l1 = l1 * al1 + sum1;
        m0r = mn0; m1r = mn1;

#pragma unroll
        for (int j = 0; j < 8; j++) {
            o[j][0] *= al0; o[j][1] *= al0;
            o[j][2] *= al1; o[j][3] *= al1;
        }

        // --- Pack P accumulator fragments into PV A fragments (registers) ---
        uint32_t pA[4][4];
#pragma unroll
        for (int kc = 0; kc < 4; kc++) {
            pA[kc][0] = packbf(s[2 * kc][0],     s[2 * kc][1]);
            pA[kc][1] = packbf(s[2 * kc][2],     s[2 * kc][3]);
            pA[kc][2] = packbf(s[2 * kc + 1][0], s[2 * kc + 1][1]);
            pA[kc][3] = packbf(s[2 * kc + 1][2], s[2 * kc + 1][3]);
        }

        // --- ctx += P · V  (V B-frags via ldmatrix.trans) ---
#pragma unroll
        for (int kc = 0; kc < 4; kc++) {
#pragma unroll
            for (int jp = 0; jp < 4; jp++) {
                uint32_t Vf[4];
                ldsm4t(Vf, vs_b + (uint32_t)((16 * kc + v_row) * 144 + 32 * jp + v_byt));
                mma_bf16(o[2 * jp],     pA[kc], &Vf[0]);
                mma_bf16(o[2 * jp + 1], pA[kc], &Vf[2]);
            }
        }
    }

    // Epilogue: normalize and store fp32
    const float inv0 = 1.f / l0, inv1 = 1.f / l1;
    const int row0 = q0 + 16 * wid + g;
#pragma unroll
    for (int j = 0; j < 8; j++) {
        float2 a, b2;
        a.x  = o[j][0] * inv0; a.y  = o[j][1] * inv0;
        b2.x = o[j][2] * inv1; b2.y = o[j][3] * inv1;
        *(float2*)&Ctx[base + (size_t)row0 * DKH + 8 * j + 2 * q]       = a;
        *(float2*)&Ctx[base + (size_t)(row0 + 8) * DKH + 8 * j + 2 * q] = b2;
    }
}

// ---------------------------------------------------------------------------
// In-place LayerNorm over last dim (1024). One block (256 thr) per row.
// ---------------------------------------------------------------------------
__global__ __launch_bounds__(256)
void layernorm_kernel(float* __restrict__ X, const float* __restrict__ gamma,
                      const float* __restrict__ beta)
{
    __shared__ float rs[8], rss[8];
    const int row = blockIdx.x;
    const int tid = threadIdx.x;

    float4 v = *(const float4*)&X[(size_t)row * DMODEL + tid * 4];
    float s  = v.x + v.y + v.z + v.w;
    float ss = v.x * v.x + v.y * v.y + v.z * v.z + v.w * v.w;

#pragma unroll
    for (int o = 16; o > 0; o >>= 1) {
        s  += __shfl_down_sync(0xffffffffu, s,  o);
        ss += __shfl_down_sync(0xffffffffu, ss, o);
    }
    const int w  = tid >> 5;
    const int ln = tid & 31;
    if (ln == 0) { rs[w] = s; rss[w] = ss; }
    __syncthreads();

    float tot = 0.f, tot2 = 0.f;
#pragma unroll
    for (int i = 0; i < 8; i++) { tot += rs[i]; tot2 += rss[i]; }
    const float mean = tot * (1.f / DMODEL);
    const float var  = tot2 * (1.f / DMODEL) - mean * mean;
    const float rstd = rsqrtf(var + 1e-6f);

    float4 g4 = *(const float4*)&gamma[tid * 4];
    float4 b4 = *(const float4*)&beta[tid * 4];
    float4 o;
    o.x = (v.x - mean) * rstd * g4.x + b4.x;
    o.y = (v.y - mean) * rstd * g4.y + b4.y;
    o.z = (v.z - mean) * rstd * g4.z + b4.z;
    o.w = (v.w - mean) * rstd * g4.w + b4.w;
    *(float4*)&X[(size_t)row * DMODEL + tid * 4] = o;
}

// ---------------------------------------------------------------------------
// Launch
// ---------------------------------------------------------------------------
extern "C" void kernel_launch(void* const* d_in, const int* in_sizes, int n_in,
                              void* d_out, int out_size)
{
    (void)in_sizes; (void)n_in; (void)out_size;
    const float* q     = (const float*)d_in[0];
    const float* k     = (const float*)d_in[1];
    const float* v     = (const float*)d_in[2];
    const float* Wq    = (const float*)d_in[3];
    const float* bq    = (const float*)d_in[4];
    const float* Wk    = (const float*)d_in[5];
    const float* bk    = (const float*)d_in[6];
    const float* Wv    = (const float*)d_in[7];
    const float* bv    = (const float*)d_in[8];
    const float* Wo    = (const float*)d_in[9];
    const float* bo    = (const float*)d_in[10];
    const float* gamma = (const float*)d_in[11];
    const float* beta  = (const float*)d_in[12];
    float* out = (float*)d_out;

    float *qp, *kp, *vp, *ctx;
    cudaGetSymbolAddress((void**)&qp,  g_qp);
    cudaGetSymbolAddress((void**)&kp,  g_kp);
    cudaGetSymbolAddress((void**)&vp,  g_vp);
    cudaGetSymbolAddress((void**)&ctx, g_ctx);

    dim3 gQKV(DMODEL / 128, MTOK / 128, 3);   // (8, 64, 3)
    gemm_qkv_bf16<<<gQKV, 256>>>(q, k, v, Wq, Wk, Wv, bq, bk, bv, qp, kp, vp);

    dim3 gAttn(SEQ / 128, BHEADS);            // (16, 64)
    attn_bf16<<<gAttn, 256>>>(qp, kp, vp, ctx);

    dim3 gGemm(DMODEL / 128, MTOK / 128);     // (8, 64)
    gemm_o_bf16<<<gGemm, 256>>>(ctx, Wo, bo, q, out);

    layernorm_kernel<<<MTOK, 256>>>(out, gamma, beta);
}

// round 12
// speedup vs baseline: 12.8519x; 1.0790x over previous
#include <cuda_runtime.h>
#include <cuda_bf16.h>
#include <math.h>
#include <stdint.h>

// B=4, S=2048, D=1024, H=16, DK=64 -> M = 8192 tokens.
// Head split reshape(B*H, S, DK) is an identity on the flat buffer.
#define MTOK   8192
#define DMODEL 1024
#define BHEADS 64
#define SEQ    2048
#define DKH    64

// Scratch (device globals, bf16: halves traffic; rounding is equivalent to
// the conversion the consumers already performed).
__device__ __nv_bfloat16 g_qp [MTOK * DMODEL];
__device__ __nv_bfloat16 g_kp [MTOK * DMODEL];
__device__ __nv_bfloat16 g_vp [MTOK * DMODEL];
__device__ __nv_bfloat16 g_ctx[MTOK * DMODEL];

// ---------------------------------------------------------------------------
// PTX helpers
// ---------------------------------------------------------------------------
__device__ __forceinline__ uint32_t packbf(float lo, float hi) {
    uint32_t r;
    asm("cvt.rn.bf16x2.f32 %0, %1, %2;" : "=r"(r) : "f"(hi), "f"(lo));
    return r;
}

__device__ __forceinline__ void ldsm4(uint32_t* r, uint32_t saddr) {
    asm volatile("ldmatrix.sync.aligned.m8n8.x4.shared.b16 {%0,%1,%2,%3}, [%4];"
                 : "=r"(r[0]), "=r"(r[1]), "=r"(r[2]), "=r"(r[3]) : "r"(saddr));
}

__device__ __forceinline__ void ldsm4t(uint32_t* r, uint32_t saddr) {
    asm volatile("ldmatrix.sync.aligned.m8n8.x4.trans.shared.b16 {%0,%1,%2,%3}, [%4];"
                 : "=r"(r[0]), "=r"(r[1]), "=r"(r[2]), "=r"(r[3]) : "r"(saddr));
}

__device__ __forceinline__ void mma_bf16(float* c, const uint32_t* a, const uint32_t* b) {
    asm volatile(
        "mma.sync.aligned.m16n8k16.row.col.f32.bf16.bf16.f32 "
        "{%0,%1,%2,%3}, {%4,%5,%6,%7}, {%8,%9}, {%0,%1,%2,%3};"
        : "+f"(c[0]), "+f"(c[1]), "+f"(c[2]), "+f"(c[3])
        : "r"(a[0]), "r"(a[1]), "r"(a[2]), "r"(a[3]), "r"(b[0]), "r"(b[1]));
}

__device__ __forceinline__ void cpasync16(uint32_t smem, const void* gmem) {
    asm volatile("cp.async.cg.shared.global [%0], [%1], 16;" :: "r"(smem), "l"(gmem));
}
#define CP_COMMIT() asm volatile("cp.async.commit_group;")
#define CP_WAIT(N)  asm volatile("cp.async.wait_group %0;" :: "n"(N))

// ---------------------------------------------------------------------------
// BF16 GEMM body. Block 128x128, BK=32, 8 warps; warp tile 64(m) x 32(n).
// XBF: input X already bf16 (no cvt in staging). CBF: output stored as bf16.
// SMEM row stride 40 bf16 (80 B). Register-prefetch double buffering.
// ---------------------------------------------------------------------------
template<bool RES, bool XBF, bool CBF>
__device__ __forceinline__
void gemm_body(const void* __restrict__ Xv, const float* __restrict__ W,
               const float* __restrict__ bias, const float* __restrict__ R,
               void* __restrict__ Cv, int m0, int n0)
{
    __shared__ __nv_bfloat16 Xs[2][128 * 40];
    __shared__ __nv_bfloat16 Ws[2][128 * 40];

    const int tid  = threadIdx.x;
    const int lane = tid & 31;
    const int wid  = tid >> 5;
    const int wm   = (wid & 1) * 64;
    const int wn   = (wid >> 1) * 32;

    float acc[4][4][4];
#pragma unroll
    for (int i = 0; i < 4; i++)
#pragma unroll
        for (int j = 0; j < 4; j++)
#pragma unroll
            for (int c = 0; c < 4; c++) acc[i][j][c] = 0.f;

    const int s_row = tid >> 3;          // +32 per it
    const int s_col = (tid & 7) * 4;

    uint2 px[4], pw[4];

    auto gload = [&](int K0) {
#pragma unroll
        for (int it = 0; it < 4; it++) {
            const int row = s_row + it * 32;
            if (XBF) {
                const __nv_bfloat16* Xb = (const __nv_bfloat16*)Xv;
                px[it] = *(const uint2*)&Xb[(size_t)(m0 + row) * DMODEL + K0 + s_col];
                // uint2 = 4 bf16 cols; replicate into both slots' layout:
                // we store 4 bf16 (8B) per thread per row (matches s_col span of 4).
            } else {
                const float* Xf = (const float*)Xv;
                float4 gx = *(const float4*)&Xf[(size_t)(m0 + row) * DMODEL + K0 + s_col];
                px[it].x = packbf(gx.x, gx.y); px[it].y = packbf(gx.z, gx.w);
            }
            float4 gw = *(const float4*)&W[(size_t)(n0 + row) * DMODEL + K0 + s_col];
            pw[it].x = packbf(gw.x, gw.y); pw[it].y = packbf(gw.z, gw.w);
        }
    };
    auto gstore = [&](int buf) {
#pragma unroll
        for (int it = 0; it < 4; it++) {
            const int row = s_row + it * 32;
            *(uint2*)&Xs[buf][row * 40 + s_col] = px[it];
            *(uint2*)&Ws[buf][row * 40 + s_col] = pw[it];
        }
    };

    const int a_row = wm + (lane & 15);
    const int a_byt = 16 * (lane >> 4);
    const int b_row = wn + 8 * (lane >> 4) + (lane & 7);
    const int b_byt = 16 * ((lane >> 3) & 1);

    gload(0);
    gstore(0);
    __syncthreads();

    for (int s = 1; s <= DMODEL / 32; s++) {
        if (s < DMODEL / 32) gload(s * 32);

        const int buf = (s - 1) & 1;
        const uint32_t xb = (uint32_t)__cvta_generic_to_shared(&Xs[buf][0]);
        const uint32_t wb = (uint32_t)__cvta_generic_to_shared(&Ws[buf][0]);
#pragma unroll
        for (int kk = 0; kk < 32; kk += 16) {
            uint32_t A[4][4], Bf[2][4];
#pragma unroll
            for (int i = 0; i < 4; i++)
                ldsm4(A[i], xb + (uint32_t)((a_row + 16 * i) * 80 + 2 * kk + a_byt));
#pragma unroll
            for (int tp = 0; tp < 2; tp++)
                ldsm4(Bf[tp], wb + (uint32_t)((b_row + 16 * tp) * 80 + 2 * kk + b_byt));
#pragma unroll
            for (int i = 0; i < 4; i++)
#pragma unroll
                for (int j = 0; j < 4; j++)
                    mma_bf16(acc[i][j], A[i], &Bf[j >> 1][(j & 1) * 2]);
        }

        if (s < DMODEL / 32) gstore(s & 1);
        __syncthreads();
    }

    // Epilogue
    const int q = lane & 3, g = lane >> 2;
#pragma unroll
    for (int i = 0; i < 4; i++) {
#pragma unroll
        for (int j = 0; j < 4; j++) {
            const int row0 = m0 + wm + 16 * i + g;
            const int col  = n0 + wn + 8 * j + 2 * q;
            float2 bi = *(const float2*)&bias[col];
            float a0 = acc[i][j][0] + bi.x, a1 = acc[i][j][1] + bi.y;
            float a2 = acc[i][j][2] + bi.x, a3 = acc[i][j][3] + bi.y;
            if (RES) {
                float2 r0 = *(const float2*)&R[(size_t)row0 * DMODEL + col];
                float2 r1 = *(const float2*)&R[(size_t)(row0 + 8) * DMODEL + col];
                a0 += r0.x; a1 += r0.y; a2 += r1.x; a3 += r1.y;
            }
            if (CBF) {
                __nv_bfloat16* Cb = (__nv_bfloat16*)Cv;
                *(uint32_t*)&Cb[(size_t)row0 * DMODEL + col]       = packbf(a0, a1);
                *(uint32_t*)&Cb[(size_t)(row0 + 8) * DMODEL + col] = packbf(a2, a3);
            } else {
                float* Cf = (float*)Cv;
                float2 o0; o0.x = a0; o0.y = a1;
                float2 o1; o1.x = a2; o1.y = a3;
                *(float2*)&Cf[(size_t)row0 * DMODEL + col]       = o0;
                *(float2*)&Cf[(size_t)(row0 + 8) * DMODEL + col] = o1;
            }
        }
    }
}

// Batched QKV projection (fp32 in -> bf16 out); blockIdx.z selects triple.
__global__ __launch_bounds__(256, 2)
void gemm_qkv_bf16(const float* __restrict__ xq, const float* __restrict__ xk,
                   const float* __restrict__ xv,
                   const float* __restrict__ Wq, const float* __restrict__ Wk,
                   const float* __restrict__ Wv,
                   const float* __restrict__ bq, const float* __restrict__ bk,
                   const float* __restrict__ bv,
                   __nv_bfloat16* __restrict__ qp, __nv_bfloat16* __restrict__ kp,
                   __nv_bfloat16* __restrict__ vp)
{
    const float *X, *W, *b;
    __nv_bfloat16* C;
    if (blockIdx.z == 0)      { X = xq; W = Wq; b = bq; C = qp; }
    else if (blockIdx.z == 1) { X = xk; W = Wk; b = bk; C = kp; }
    else                      { X = xv; W = Wv; b = bv; C = vp; }
    gemm_body<false, false, true>(X, W, b, nullptr, C, blockIdx.y * 128, blockIdx.x * 128);
}

// O projection (bf16 ctx in -> fp32 out) with residual add.
__global__ __launch_bounds__(256, 2)
void gemm_o_bf16(const __nv_bfloat16* __restrict__ X, const float* __restrict__ W,
                 const float* __restrict__ bias, const float* __restrict__ R,
                 float* __restrict__ C)
{
    gemm_body<true, true, false>(X, W, bias, R, C, blockIdx.y * 128, blockIdx.x * 128);
}

// ---------------------------------------------------------------------------
// BF16 flash attention with cp.async double-buffered K/V.
// Block: q-tile 128, key tiles of 64, 8 warps (16 q rows each).
// P stays in registers; V B-frags via ldmatrix.trans. Row stride 72 bf16.
// Score scale 1/8 applied post-MMA (commutes with max).
// ---------------------------------------------------------------------------
__global__ __launch_bounds__(256)
void attn_bf16(const __nv_bfloat16* __restrict__ Qp,
               const __nv_bfloat16* __restrict__ Kp,
               const __nv_bfloat16* __restrict__ Vp,
               __nv_bfloat16* __restrict__ Ctx)
{
    extern __shared__ __nv_bfloat16 smdyn[];
    __nv_bfloat16* Qs = smdyn;               // 128*72
    __nv_bfloat16* Ks = Qs + 128 * 72;       // 2 stages * 64*72
    __nv_bfloat16* Vs = Ks + 2 * 64 * 72;    // 2 stages * 64*72

    const int tid  = threadIdx.x;
    const int lane = tid & 31;
    const int wid  = tid >> 5;
    const int bh   = blockIdx.y;
    const int q0   = blockIdx.x * 128;
    const size_t base = (size_t)bh * SEQ * DKH;

    const int q = lane & 3, g = lane >> 2;

    // ldmatrix address components (byte offsets; row stride 144 B)
    const int a_row = 16 * wid + (lane & 15);
    const int a_byt = 16 * (lane >> 4);
    const int k_row = 8 * (lane >> 4) + (lane & 7);
    const int k_byt = 16 * ((lane >> 3) & 1);
    const int v_row = 8 * ((lane >> 3) & 1) + (lane & 7);
    const int v_byt = 16 * (lane >> 4);

    const uint32_t qs_b = (uint32_t)__cvta_generic_to_shared(Qs);
    const uint32_t ks_b = (uint32_t)__cvta_generic_to_shared(Ks);
    const uint32_t vs_b = (uint32_t)__cvta_generic_to_shared(Vs);

    // cp.async chunk mapping: chunk c -> row=c>>3, col16=c&7 (8 x 16B per 128B row)
    const int c_row0 = tid >> 3;         // chunk tid
    const int c_col0 = (tid & 7) * 16;   // byte col

    // --- Stage Q (128 rows = 1024 chunks, 4 per thread) + KV stage 0, one group
    {
        const __nv_bfloat16* Qg = Qp + base + (size_t)q0 * DKH;
#pragma unroll
        for (int it = 0; it < 4; it++) {
            const int row = c_row0 + it * 32;
            cpasync16(qs_b + (uint32_t)(row * 144 + c_col0),
                      (const char*)Qg + (size_t)row * 128 + c_col0);
        }
        const __nv_bfloat16* Kg = Kp + base;
        const __nv_bfloat16* Vg = Vp + base;
#pragma unroll
        for (int it = 0; it < 2; it++) {
            const int row = c_row0 + it * 32;
            cpasync16(ks_b + (uint32_t)(row * 144 + c_col0),
                      (const char*)Kg + (size_t)row * 128 + c_col0);
            cpasync16(vs_b + (uint32_t)(row * 144 + c_col0),
                      (const char*)Vg + (size_t)row * 128 + c_col0);
        }
        CP_COMMIT();
    }

    float m0r = -INFINITY, m1r = -INFINITY, l0 = 0.f, l1 = 0.f;
    float o[8][4];
#pragma unroll
    for (int j = 0; j < 8; j++)
#pragma unroll
        for (int c = 0; c < 4; c++) o[j][c] = 0.f;

    const int NT = SEQ / 64;   // 32
    for (int kt = 0; kt < NT; kt++) {
        const int cur = kt & 1;
        // Prefetch stage kt+1 into buffer cur^1
        if (kt + 1 < NT) {
            const __nv_bfloat16* Kg = Kp + base + (size_t)((kt + 1) * 64) * DKH;
            const __nv_bfloat16* Vg = Vp + base + (size_t)((kt + 1) * 64) * DKH;
            const uint32_t kb = ks_b + (uint32_t)((cur ^ 1) * 64 * 144);
            const uint32_t vb = vs_b + (uint32_t)((cur ^ 1) * 64 * 144);
#pragma unroll
            for (int it = 0; it < 2; it++) {
                const int row = c_row0 + it * 32;
                cpasync16(kb + (uint32_t)(row * 144 + c_col0),
                          (const char*)Kg + (size_t)row * 128 + c_col0);
                cpasync16(vb + (uint32_t)(row * 144 + c_col0),
                          (const char*)Vg + (size_t)row * 128 + c_col0);
            }
            CP_COMMIT();
            CP_WAIT(1);
        } else {
            CP_WAIT(0);
        }
        __syncthreads();

        const uint32_t kcur = ks_b + (uint32_t)(cur * 64 * 144);
        const uint32_t vcur = vs_b + (uint32_t)(cur * 64 * 144);

        // --- Scores: S[16 x 64] per warp ---
        float s[8][4];
#pragma unroll
        for (int j = 0; j < 8; j++)
#pragma unroll
            for (int c = 0; c < 4; c++) s[j][c] = 0.f;

#pragma unroll
        for (int kk = 0; kk < 64; kk += 16) {
            uint32_t A[4], Bf[4][4];
            ldsm4(A, qs_b + (uint32_t)(a_row * 144 + 2 * kk + a_byt));
#pragma unroll
            for (int tp = 0; tp < 4; tp++)
                ldsm4(Bf[tp], kcur + (uint32_t)((k_row + 16 * tp) * 144 + 2 * kk + k_byt));
#pragma unroll
            for (int j = 0; j < 8; j++)
                mma_bf16(s[j], A, &Bf[j >> 1][(j & 1) * 2]);
        }

        // Apply 1/sqrt(DK)=0.125 scale (commutes with max)
#pragma unroll
        for (int j = 0; j < 8; j++) {
            s[j][0] *= 0.125f; s[j][1] *= 0.125f;
            s[j][2] *= 0.125f; s[j][3] *= 0.125f;
        }

        // --- Online softmax (rows r0 = 16*wid+g, r1 = r0+8) ---
        float mx0 = s[0][0], mx1 = s[0][2];
#pragma unroll
        for (int j = 0; j < 8; j++) {
            mx0 = fmaxf(mx0, fmaxf(s[j][0], s[j][1]));
            mx1 = fmaxf(mx1, fmaxf(s[j][2], s[j][3]));
        }
        mx0 = fmaxf(mx0, __shfl_xor_sync(0xffffffffu, mx0, 1));
        mx0 = fmaxf(mx0, __shfl_xor_sync(0xffffffffu, mx0, 2));
        mx1 = fmaxf(mx1, __shfl_xor_sync(0xffffffffu, mx1, 1));
        mx1 = fmaxf(mx1, __shfl_xor_sync(0xffffffffu, mx1, 2));
        const float mn0 = fmaxf(m0r, mx0), mn1 = fmaxf(m1r, mx1);
        const float al0 = __expf(m0r - mn0), al1 = __expf(m1r - mn1);

        float sum0 = 0.f, sum1 = 0.f;
#pragma unroll
        for (int j = 0; j < 8; j++) {
            s[j][0] = __expf(s[j][0] - mn0);
            s[j][1] = __expf(s[j][1] - mn0);
            s[j][2] = __expf(s[j][2] - mn1);
            s[j][3] = __expf(s[j][3] - mn1);
            sum0 += s[j][0] + s[j][1];
            sum1 += s[j][2] + s[j][3];
        }
        sum0 += __shfl_xor_sync(0xffffffffu, sum0, 1);
        sum0 += __shfl_xor_sync(0xffffffffu, sum0, 2);
        sum1 += __shfl_xor_sync(0xffffffffu, sum1, 1);
        sum1 += __shfl_xor_sync(0xffffffffu, sum1, 2);
        l0 = l0 * al0 + sum0;
        l1 = l1 * al1 + sum1;
        m0r = mn0; m1r = mn1;

#pragma unroll
        for (int j = 0; j < 8; j++) {
            o[j][0] *= al0; o[j][1] *= al0;
            o[j][2] *= al1; o[j][3] *= al1;
        }

        // --- Pack P accumulator fragments into PV A fragments (registers) ---
        uint32_t pA[4][4];
#pragma unroll
        for (int kc = 0; kc < 4; kc++) {
            pA[kc][0] = packbf(s[2 * kc][0],     s[2 * kc][1]);
            pA[kc][1] = packbf(s[2 * kc][2],     s[2 * kc][3]);
            pA[kc][2] = packbf(s[2 * kc + 1][0], s[2 * kc + 1][1]);
            pA[kc][3] = packbf(s[2 * kc + 1][2], s[2 * kc + 1][3]);
        }

        // --- ctx += P · V  (V B-frags via ldmatrix.trans) ---
#pragma unroll
        for (int kc = 0; kc < 4; kc++) {
#pragma unroll
            for (int jp = 0; jp < 4; jp++) {
                uint32_t Vf[4];
                ldsm4t(Vf, vcur + (uint32_t)((16 * kc + v_row) * 144 + 32 * jp + v_byt));
                mma_bf16(o[2 * jp],     pA[kc], &Vf[0]);
                mma_bf16(o[2 * jp + 1], pA[kc], &Vf[2]);
            }
        }
        __syncthreads();   // all reads of cur done before next prefetch overwrites
    }

    // Epilogue: normalize, round to bf16, store
    const float inv0 = 1.f / l0, inv1 = 1.f / l1;
    const int row0 = q0 + 16 * wid + g;
#pragma unroll
    for (int j = 0; j < 8; j++) {
        uint32_t u0 = packbf(o[j][0] * inv0, o[j][1] * inv0);
        uint32_t u1 = packbf(o[j][2] * inv1, o[j][3] * inv1);
        *(uint32_t*)&Ctx[base + (size_t)row0 * DKH + 8 * j + 2 * q]       = u0;
        *(uint32_t*)&Ctx[base + (size_t)(row0 + 8) * DKH + 8 * j + 2 * q] = u1;
    }
}

// ---------------------------------------------------------------------------
// In-place LayerNorm over last dim (1024). One block (256 thr) per row.
// ---------------------------------------------------------------------------
__global__ __launch_bounds__(256)
void layernorm_kernel(float* __restrict__ X, const float* __restrict__ gamma,
                      const float* __restrict__ beta)
{
    __shared__ float rs[8], rss[8];
    const int row = blockIdx.x;
    const int tid = threadIdx.x;

    float4 v = *(const float4*)&X[(size_t)row * DMODEL + tid * 4];
    float s  = v.x + v.y + v.z + v.w;
    float ss = v.x * v.x + v.y * v.y + v.z * v.z + v.w * v.w;

#pragma unroll
    for (int o = 16; o > 0; o >>= 1) {
        s  += __shfl_down_sync(0xffffffffu, s,  o);
        ss += __shfl_down_sync(0xffffffffu, ss, o);
    }
    const int w  = tid >> 5;
    const int ln = tid & 31;
    if (ln == 0) { rs[w] = s; rss[w] = ss; }
    __syncthreads();

    float tot = 0.f, tot2 = 0.f;
#pragma unroll
    for (int i = 0; i < 8; i++) { tot += rs[i]; tot2 += rss[i]; }
    const float mean = tot * (1.f / DMODEL);
    const float var  = tot2 * (1.f / DMODEL) - mean * mean;
    const float rstd = rsqrtf(var + 1e-6f);

    float4 g4 = *(const float4*)&gamma[tid * 4];
    float4 b4 = *(const float4*)&beta[tid * 4];
    float4 o;
    o.x = (v.x - mean) * rstd * g4.x + b4.x;
    o.y = (v.y - mean) * rstd * g4.y + b4.y;
    o.z = (v.z - mean) * rstd * g4.z + b4.z;
    o.w = (v.w - mean) * rstd * g4.w + b4.w;
    *(float4*)&X[(size_t)row * DMODEL + tid * 4] = o;
}

// ---------------------------------------------------------------------------
// Launch
// ---------------------------------------------------------------------------
extern "C" void kernel_launch(void* const* d_in, const int* in_sizes, int n_in,
                              void* d_out, int out_size)
{
    (void)in_sizes; (void)n_in; (void)out_size;
    const float* q     = (const float*)d_in[0];
    const float* k     = (const float*)d_in[1];
    const float* v     = (const float*)d_in[2];
    const float* Wq    = (const float*)d_in[3];
    const float* bq    = (const float*)d_in[4];
    const float* Wk    = (const float*)d_in[5];
    const float* bk    = (const float*)d_in[6];
    const float* Wv    = (const float*)d_in[7];
    const float* bv    = (const float*)d_in[8];
    const float* Wo    = (const float*)d_in[9];
    const float* bo    = (const float*)d_in[10];
    const float* gamma = (const float*)d_in[11];
    const float* beta  = (const float*)d_in[12];
    float* out = (float*)d_out;

    __nv_bfloat16 *qp, *kp, *vp, *ctx;
    cudaGetSymbolAddress((void**)&qp,  g_qp);
    cudaGetSymbolAddress((void**)&kp,  g_kp);
    cudaGetSymbolAddress((void**)&vp,  g_vp);
    cudaGetSymbolAddress((void**)&ctx, g_ctx);

    // Attention dynamic smem: Q(128*72) + 2*K(64*72) + 2*V(64*72) bf16
    static int smem_set = 0;
    const int attn_smem = (128 * 72 + 4 * 64 * 72) * 2;
    if (!smem_set) {
        cudaFuncSetAttribute(attn_bf16, cudaFuncAttributeMaxDynamicSharedMemorySize, attn_smem);
        smem_set = 1;
    }

    dim3 gQKV(DMODEL / 128, MTOK / 128, 3);   // (8, 64, 3)
    gemm_qkv_bf16<<<gQKV, 256>>>(q, k, v, Wq, Wk, Wv, bq, bk, bv, qp, kp, vp);

    dim3 gAttn(SEQ / 128, BHEADS);            // (16, 64)
    attn_bf16<<<gAttn, 256, attn_smem>>>(qp, kp, vp, ctx);

    dim3 gGemm(DMODEL / 128, MTOK / 128);     // (8, 64)
    gemm_o_bf16<<<gGemm, 256>>>(ctx, Wo, bo, q, out);

    layernorm_kernel<<<MTOK, 256>>>(out, gamma, beta);
}

// round 13
// speedup vs baseline: 13.6994x; 1.0659x over previous
#include <cuda_runtime.h>
#include <cuda_bf16.h>
#include <math.h>
#include <stdint.h>

// B=4, S=2048, D=1024, H=16, DK=64 -> M = 8192 tokens.
// Head split reshape(B*H, S, DK) is an identity on the flat buffer.
#define MTOK   8192
#define DMODEL 1024
#define BHEADS 64
#define SEQ    2048
#define DKH    64

// Scratch (device globals; bf16 rounding equals the cvt consumers did anyway)
__device__ __nv_bfloat16 g_qp [MTOK * DMODEL];
__device__ __nv_bfloat16 g_kp [MTOK * DMODEL];
__device__ __nv_bfloat16 g_vp [MTOK * DMODEL];
__device__ __nv_bfloat16 g_ctx[MTOK * DMODEL];
// Pre-converted bf16 inputs and weights
__device__ __nv_bfloat16 g_qin[MTOK * DMODEL];
__device__ __nv_bfloat16 g_kin[MTOK * DMODEL];
__device__ __nv_bfloat16 g_vin[MTOK * DMODEL];
__device__ __nv_bfloat16 g_wq [DMODEL * DMODEL];
__device__ __nv_bfloat16 g_wk [DMODEL * DMODEL];
__device__ __nv_bfloat16 g_wv [DMODEL * DMODEL];
__device__ __nv_bfloat16 g_wo [DMODEL * DMODEL];

// ---------------------------------------------------------------------------
// PTX helpers
// ---------------------------------------------------------------------------
__device__ __forceinline__ uint32_t packbf(float lo, float hi) {
    uint32_t r;
    asm("cvt.rn.bf16x2.f32 %0, %1, %2;" : "=r"(r) : "f"(hi), "f"(lo));
    return r;
}

__device__ __forceinline__ void ldsm4(uint32_t* r, uint32_t saddr) {
    asm volatile("ldmatrix.sync.aligned.m8n8.x4.shared.b16 {%0,%1,%2,%3}, [%4];"
                 : "=r"(r[0]), "=r"(r[1]), "=r"(r[2]), "=r"(r[3]) : "r"(saddr));
}

__device__ __forceinline__ void ldsm4t(uint32_t* r, uint32_t saddr) {
    asm volatile("ldmatrix.sync.aligned.m8n8.x4.trans.shared.b16 {%0,%1,%2,%3}, [%4];"
                 : "=r"(r[0]), "=r"(r[1]), "=r"(r[2]), "=r"(r[3]) : "r"(saddr));
}

__device__ __forceinline__ void mma_bf16(float* c, const uint32_t* a, const uint32_t* b) {
    asm volatile(
        "mma.sync.aligned.m16n8k16.row.col.f32.bf16.bf16.f32 "
        "{%0,%1,%2,%3}, {%4,%5,%6,%7}, {%8,%9}, {%0,%1,%2,%3};"
        : "+f"(c[0]), "+f"(c[1]), "+f"(c[2]), "+f"(c[3])
        : "r"(a[0]), "r"(a[1]), "r"(a[2]), "r"(a[3]), "r"(b[0]), "r"(b[1]));
}

__device__ __forceinline__ void cpasync16(uint32_t smem, const void* gmem) {
    asm volatile("cp.async.cg.shared.global [%0], [%1], 16;" :: "r"(smem), "l"(gmem));
}
#define CP_COMMIT() asm volatile("cp.async.commit_group;")
#define CP_WAIT(N)  asm volatile("cp.async.wait_group %0;" :: "n"(N))

// ---------------------------------------------------------------------------
// fp32 -> bf16 conversion kernels (one-time per launch)
// ---------------------------------------------------------------------------
__global__ __launch_bounds__(256)
void cvt_inputs(const float* __restrict__ a, const float* __restrict__ b,
                const float* __restrict__ c,
                __nv_bfloat16* __restrict__ oa, __nv_bfloat16* __restrict__ ob,
                __nv_bfloat16* __restrict__ oc)
{
    const float* in; __nv_bfloat16* out;
    if (blockIdx.y == 0)      { in = a; out = oa; }
    else if (blockIdx.y == 1) { in = b; out = ob; }
    else                      { in = c; out = oc; }
    const size_t i = ((size_t)blockIdx.x * 256 + threadIdx.x) * 4;
    float4 v = *(const float4*)&in[i];
    uint2 u; u.x = packbf(v.x, v.y); u.y = packbf(v.z, v.w);
    *(uint2*)&out[i] = u;
}

__global__ __launch_bounds__(256)
void cvt_weights(const float* __restrict__ a, const float* __restrict__ b,
                 const float* __restrict__ c, const float* __restrict__ d,
                 __nv_bfloat16* __restrict__ oa, __nv_bfloat16* __restrict__ ob,
                 __nv_bfloat16* __restrict__ oc, __nv_bfloat16* __restrict__ od)
{
    const float* in; __nv_bfloat16* out;
    if (blockIdx.y == 0)      { in = a; out = oa; }
    else if (blockIdx.y == 1) { in = b; out = ob; }
    else if (blockIdx.y == 2) { in = c; out = oc; }
    else                      { in = d; out = od; }
    const size_t i = ((size_t)blockIdx.x * 256 + threadIdx.x) * 4;
    float4 v = *(const float4*)&in[i];
    uint2 u; u.x = packbf(v.x, v.y); u.y = packbf(v.z, v.w);
    *(uint2*)&out[i] = u;
}

// ---------------------------------------------------------------------------
// All-bf16 GEMM body with cp.async double buffering.
// Block 128x128, BK=32, 8 warps; warp tile 64(m) x 32(n). m16n8k16 MMA.
// SMEM row stride 40 bf16 (80 B). CBF: bf16 output; RES: + residual (fp32).
// ---------------------------------------------------------------------------
template<bool RES, bool CBF>
__device__ __forceinline__
void gemm_body(const __nv_bfloat16* __restrict__ X, const __nv_bfloat16* __restrict__ W,
               const float* __restrict__ bias, const float* __restrict__ R,
               void* __restrict__ Cv, int m0, int n0)
{
    __shared__ __nv_bfloat16 Xs[2][128 * 40];
    __shared__ __nv_bfloat16 Ws[2][128 * 40];

    const int tid  = threadIdx.x;
    const int lane = tid & 31;
    const int wid  = tid >> 5;
    const int wm   = (wid & 1) * 64;
    const int wn   = (wid >> 1) * 32;

    float acc[4][4][4];
#pragma unroll
    for (int i = 0; i < 4; i++)
#pragma unroll
        for (int j = 0; j < 4; j++)
#pragma unroll
            for (int c = 0; c < 4; c++) acc[i][j][c] = 0.f;

    const uint32_t xs0 = (uint32_t)__cvta_generic_to_shared(&Xs[0][0]);
    const uint32_t ws0 = (uint32_t)__cvta_generic_to_shared(&Ws[0][0]);

    // cp.async staging: 512 chunks of 16B per operand per stage (2 per thread).
    // chunk idx -> row = idx>>2, byte col = (idx&3)*16  (row = 64B of data)
    const int c_row = tid >> 2;          // +64 for second chunk
    const int c_col = (tid & 3) * 16;

    auto stage = [&](int K0, int buf) {
        const uint32_t xb = xs0 + (uint32_t)(buf * 128 * 80);
        const uint32_t wb = ws0 + (uint32_t)(buf * 128 * 80);
#pragma unroll
        for (int it = 0; it < 2; it++) {
            const int row = c_row + it * 64;
            cpasync16(xb + (uint32_t)(row * 80 + c_col),
                      (const char*)&X[(size_t)(m0 + row) * DMODEL + K0] + c_col);
            cpasync16(wb + (uint32_t)(row * 80 + c_col),
                      (const char*)&W[(size_t)(n0 + row) * DMODEL + K0] + c_col);
        }
    };

    // ldmatrix address components (byte offsets within 80B rows)
    const int a_row = wm + (lane & 15);
    const int a_byt = 16 * (lane >> 4);
    const int b_row = wn + 8 * (lane >> 4) + (lane & 7);
    const int b_byt = 16 * ((lane >> 3) & 1);

    stage(0, 0);
    CP_COMMIT();

    const int NS = DMODEL / 32;   // 32 stages
    for (int s = 0; s < NS; s++) {
        const int buf = s & 1;
        if (s + 1 < NS) {
            stage((s + 1) * 32, buf ^ 1);
            CP_COMMIT();
            CP_WAIT(1);
        } else {
            CP_WAIT(0);
        }
        __syncthreads();

        const uint32_t xb = xs0 + (uint32_t)(buf * 128 * 80);
        const uint32_t wb = ws0 + (uint32_t)(buf * 128 * 80);
#pragma unroll
        for (int kk = 0; kk < 32; kk += 16) {
            uint32_t A[4][4], Bf[2][4];
#pragma unroll
            for (int i = 0; i < 4; i++)
                ldsm4(A[i], xb + (uint32_t)((a_row + 16 * i) * 80 + 2 * kk + a_byt));
#pragma unroll
            for (int tp = 0; tp < 2; tp++)
                ldsm4(Bf[tp], wb + (uint32_t)((b_row + 16 * tp) * 80 + 2 * kk + b_byt));
#pragma unroll
            for (int i = 0; i < 4; i++)
#pragma unroll
                for (int j = 0; j < 4; j++)
                    mma_bf16(acc[i][j], A[i], &Bf[j >> 1][(j & 1) * 2]);
        }
        __syncthreads();   // all reads of buf done before it is overwritten
    }

    // Epilogue
    const int q = lane & 3, g = lane >> 2;
#pragma unroll
    for (int i = 0; i < 4; i++) {
#pragma unroll
        for (int j = 0; j < 4; j++) {
            const int row0 = m0 + wm + 16 * i + g;
            const int col  = n0 + wn + 8 * j + 2 * q;
            float2 bi = *(const float2*)&bias[col];
            float a0 = acc[i][j][0] + bi.x, a1 = acc[i][j][1] + bi.y;
            float a2 = acc[i][j][2] + bi.x, a3 = acc[i][j][3] + bi.y;
            if (RES) {
                float2 r0 = *(const float2*)&R[(size_t)row0 * DMODEL + col];
                float2 r1 = *(const float2*)&R[(size_t)(row0 + 8) * DMODEL + col];
                a0 += r0.x; a1 += r0.y; a2 += r1.x; a3 += r1.y;
            }
            if (CBF) {
                __nv_bfloat16* Cb = (__nv_bfloat16*)Cv;
                *(uint32_t*)&Cb[(size_t)row0 * DMODEL + col]       = packbf(a0, a1);
                *(uint32_t*)&Cb[(size_t)(row0 + 8) * DMODEL + col] = packbf(a2, a3);
            } else {
                float* Cf = (float*)Cv;
                float2 o0; o0.x = a0; o0.y = a1;
                float2 o1; o1.x = a2; o1.y = a3;
                *(float2*)&Cf[(size_t)row0 * DMODEL + col]       = o0;
                *(float2*)&Cf[(size_t)(row0 + 8) * DMODEL + col] = o1;
            }
        }
    }
}

// Batched QKV projection (bf16 in -> bf16 out); blockIdx.z selects triple.
__global__ __launch_bounds__(256, 2)
void gemm_qkv_bf16(const __nv_bfloat16* __restrict__ xq, const __nv_bfloat16* __restrict__ xk,
                   const __nv_bfloat16* __restrict__ xv,
                   const __nv_bfloat16* __restrict__ Wq, const __nv_bfloat16* __restrict__ Wk,
                   const __nv_bfloat16* __restrict__ Wv,
                   const float* __restrict__ bq, const float* __restrict__ bk,
                   const float* __restrict__ bv,
                   __nv_bfloat16* __restrict__ qp, __nv_bfloat16* __restrict__ kp,
                   __nv_bfloat16* __restrict__ vp)
{
    const __nv_bfloat16 *X, *W;
    const float* b;
    __nv_bfloat16* C;
    if (blockIdx.z == 0)      { X = xq; W = Wq; b = bq; C = qp; }
    else if (blockIdx.z == 1) { X = xk; W = Wk; b = bk; C = kp; }
    else                      { X = xv; W = Wv; b = bv; C = vp; }
    gemm_body<false, true>(X, W, b, nullptr, C, blockIdx.y * 128, blockIdx.x * 128);
}

// O projection (bf16 in -> fp32 out) with fp32 residual add.
__global__ __launch_bounds__(256, 2)
void gemm_o_bf16(const __nv_bfloat16* __restrict__ X, const __nv_bfloat16* __restrict__ W,
                 const float* __restrict__ bias, const float* __restrict__ R,
                 float* __restrict__ C)
{
    gemm_body<true, false>(X, W, bias, R, C, blockIdx.y * 128, blockIdx.x * 128);
}

// ---------------------------------------------------------------------------
// BF16 flash attention with cp.async double-buffered K/V.
// Block: q-tile 128, key tiles of 64, 8 warps (16 q rows each).
// P stays in registers; V B-frags via ldmatrix.trans. Row stride 72 bf16.
// Score scale 1/8 applied post-MMA (commutes with max).
// ---------------------------------------------------------------------------
__global__ __launch_bounds__(256)
void attn_bf16(const __nv_bfloat16* __restrict__ Qp,
               const __nv_bfloat16* __restrict__ Kp,
               const __nv_bfloat16* __restrict__ Vp,
               __nv_bfloat16* __restrict__ Ctx)
{
    extern __shared__ __nv_bfloat16 smdyn[];
    __nv_bfloat16* Qs = smdyn;               // 128*72
    __nv_bfloat16* Ks = Qs + 128 * 72;       // 2 stages * 64*72
    __nv_bfloat16* Vs = Ks + 2 * 64 * 72;    // 2 stages * 64*72

    const int tid  = threadIdx.x;
    const int lane = tid & 31;
    const int wid  = tid >> 5;
    const int bh   = blockIdx.y;
    const int q0   = blockIdx.x * 128;
    const size_t base = (size_t)bh * SEQ * DKH;

    const int q = lane & 3, g = lane >> 2;

    const int a_row = 16 * wid + (lane & 15);
    const int a_byt = 16 * (lane >> 4);
    const int k_row = 8 * (lane >> 4) + (lane & 7);
    const int k_byt = 16 * ((lane >> 3) & 1);
    const int v_row = 8 * ((lane >> 3) & 1) + (lane & 7);
    const int v_byt = 16 * (lane >> 4);

    const uint32_t qs_b = (uint32_t)__cvta_generic_to_shared(Qs);
    const uint32_t ks_b = (uint32_t)__cvta_generic_to_shared(Ks);
    const uint32_t vs_b = (uint32_t)__cvta_generic_to_shared(Vs);

    const int c_row0 = tid >> 3;
    const int c_col0 = (tid & 7) * 16;

    {
        const __nv_bfloat16* Qg = Qp + base + (size_t)q0 * DKH;
#pragma unroll
        for (int it = 0; it < 4; it++) {
            const int row = c_row0 + it * 32;
            cpasync16(qs_b + (uint32_t)(row * 144 + c_col0),
                      (const char*)Qg + (size_t)row * 128 + c_col0);
        }
        const __nv_bfloat16* Kg = Kp + base;
        const __nv_bfloat16* Vg = Vp + base;
#pragma unroll
        for (int it = 0; it < 2; it++) {
            const int row = c_row0 + it * 32;
            cpasync16(ks_b + (uint32_t)(row * 144 + c_col0),
                      (const char*)Kg + (size_t)row * 128 + c_col0);
            cpasync16(vs_b + (uint32_t)(row * 144 + c_col0),
                      (const char*)Vg + (size_t)row * 128 + c_col0);
        }
        CP_COMMIT();
    }

    float m0r = -INFINITY, m1r = -INFINITY, l0 = 0.f, l1 = 0.f;
    float o[8][4];
#pragma unroll
    for (int j = 0; j < 8; j++)
#pragma unroll
        for (int c = 0; c < 4; c++) o[j][c] = 0.f;

    const int NT = SEQ / 64;
    for (int kt = 0; kt < NT; kt++) {
        const int cur = kt & 1;
        if (kt + 1 < NT) {
            const __nv_bfloat16* Kg = Kp + base + (size_t)((kt + 1) * 64) * DKH;
            const __nv_bfloat16* Vg = Vp + base + (size_t)((kt + 1) * 64) * DKH;
            const uint32_t kb = ks_b + (uint32_t)((cur ^ 1) * 64 * 144);
            const uint32_t vb = vs_b + (uint32_t)((cur ^ 1) * 64 * 144);
#pragma unroll
            for (int it = 0; it < 2; it++) {
                const int row = c_row0 + it * 32;
                cpasync16(kb + (uint32_t)(row * 144 + c_col0),
                          (const char*)Kg + (size_t)row * 128 + c_col0);
                cpasync16(vb + (uint32_t)(row * 144 + c_col0),
                          (const char*)Vg + (size_t)row * 128 + c_col0);
            }
            CP_COMMIT();
            CP_WAIT(1);
        } else {
            CP_WAIT(0);
        }
        __syncthreads();

        const uint32_t kcur = ks_b + (uint32_t)(cur * 64 * 144);
        const uint32_t vcur = vs_b + (uint32_t)(cur * 64 * 144);

        float s[8][4];
#pragma unroll
        for (int j = 0; j < 8; j++)
#pragma unroll
            for (int c = 0; c < 4; c++) s[j][c] = 0.f;

#pragma unroll
        for (int kk = 0; kk < 64; kk += 16) {
            uint32_t A[4], Bf[4][4];
            ldsm4(A, qs_b + (uint32_t)(a_row * 144 + 2 * kk + a_byt));
#pragma unroll
            for (int tp = 0; tp < 4; tp++)
                ldsm4(Bf[tp], kcur + (uint32_t)((k_row + 16 * tp) * 144 + 2 * kk + k_byt));
#pragma unroll
            for (int j = 0; j < 8; j++)
                mma_bf16(s[j], A, &Bf[j >> 1][(j & 1) * 2]);
        }

#pragma unroll
        for (int j = 0; j < 8; j++) {
            s[j][0] *= 0.125f; s[j][1] *= 0.125f;
            s[j][2] *= 0.125f; s[j][3] *= 0.125f;
        }

        float mx0 = s[0][0], mx1 = s[0][2];
#pragma unroll
        for (int j = 0; j < 8; j++) {
            mx0 = fmaxf(mx0, fmaxf(s[j][0], s[j][1]));
            mx1 = fmaxf(mx1, fmaxf(s[j][2], s[j][3]));
        }
        mx0 = fmaxf(mx0, __shfl_xor_sync(0xffffffffu, mx0, 1));
        mx0 = fmaxf(mx0, __shfl_xor_sync(0xffffffffu, mx0, 2));
        mx1 = fmaxf(mx1, __shfl_xor_sync(0xffffffffu, mx1, 1));
        mx1 = fmaxf(mx1, __shfl_xor_sync(0xffffffffu, mx1, 2));
        const float mn0 = fmaxf(m0r, mx0), mn1 = fmaxf(m1r, mx1);
        const float al0 = __expf(m0r - mn0), al1 = __expf(m1r - mn1);

        float sum0 = 0.f, sum1 = 0.f;
#pragma unroll
        for (int j = 0; j < 8; j++) {
            s[j][0] = __expf(s[j][0] - mn0);
            s[j][1] = __expf(s[j][1] - mn0);
            s[j][2] = __expf(s[j][2] - mn1);
            s[j][3] = __expf(s[j][3] - mn1);
            sum0 += s[j][0] + s[j][1];
            sum1 += s[j][2] + s[j][3];
        }
        sum0 += __shfl_xor_sync(0xffffffffu, sum0, 1);
        sum0 += __shfl_xor_sync(0xffffffffu, sum0, 2);
        sum1 += __shfl_xor_sync(0xffffffffu, sum1, 1);
        sum1 += __shfl_xor_sync(0xffffffffu, sum1, 2);
        l0 = l0 * al0 + sum0;
        l1 = l1 * al1 + sum1;
        m0r = mn0; m1r = mn1;

#pragma unroll
        for (int j = 0; j < 8; j++) {
            o[j][0] *= al0; o[j][1] *= al0;
            o[j][2] *= al1; o[j][3] *= al1;
        }

        uint32_t pA[4][4];
#pragma unroll
        for (int kc = 0; kc < 4; kc++) {
            pA[kc][0] = packbf(s[2 * kc][0],     s[2 * kc][1]);
            pA[kc][1] = packbf(s[2 * kc][2],     s[2 * kc][3]);
            pA[kc][2] = packbf(s[2 * kc + 1][0], s[2 * kc + 1][1]);
            pA[kc][3] = packbf(s[2 * kc + 1][2], s[2 * kc + 1][3]);
        }

#pragma unroll
        for (int kc = 0; kc < 4; kc++) {
#pragma unroll
            for (int jp = 0; jp < 4; jp++) {
                uint32_t Vf[4];
                ldsm4t(Vf, vcur + (uint32_t)((16 * kc + v_row) * 144 + 32 * jp + v_byt));
                mma_bf16(o[2 * jp],     pA[kc], &Vf[0]);
                mma_bf16(o[2 * jp + 1], pA[kc], &Vf[2]);
            }
        }
        __syncthreads();
    }

    const float inv0 = 1.f / l0, inv1 = 1.f / l1;
    const int row0 = q0 + 16 * wid + g;
#pragma unroll
    for (int j = 0; j < 8; j++) {
        uint32_t u0 = packbf(o[j][0] * inv0, o[j][1] * inv0);
        uint32_t u1 = packbf(o[j][2] * inv1, o[j][3] * inv1);
        *(uint32_t*)&Ctx[base + (size_t)row0 * DKH + 8 * j + 2 * q]       = u0;
        *(uint32_t*)&Ctx[base + (size_t)(row0 + 8) * DKH + 8 * j + 2 * q] = u1;
    }
}

// ---------------------------------------------------------------------------
// In-place LayerNorm over last dim (1024). One block (256 thr) per row.
// ---------------------------------------------------------------------------
__global__ __launch_bounds__(256)
void layernorm_kernel(float* __restrict__ X, const float* __restrict__ gamma,
                      const float* __restrict__ beta)
{
    __shared__ float rs[8], rss[8];
    const int row = blockIdx.x;
    const int tid = threadIdx.x;

    float4 v = *(const float4*)&X[(size_t)row * DMODEL + tid * 4];
    float s  = v.x + v.y + v.z + v.w;
    float ss = v.x * v.x + v.y * v.y + v.z * v.z + v.w * v.w;

#pragma unroll
    for (int o = 16; o > 0; o >>= 1) {
        s  += __shfl_down_sync(0xffffffffu, s,  o);
        ss += __shfl_down_sync(0xffffffffu, ss, o);
    }
    const int w  = tid >> 5;
    const int ln = tid & 31;
    if (ln == 0) { rs[w] = s; rss[w] = ss; }
    __syncthreads();

    float tot = 0.f, tot2 = 0.f;
#pragma unroll
    for (int i = 0; i < 8; i++) { tot += rs[i]; tot2 += rss[i]; }
    const float mean = tot * (1.f / DMODEL);
    const float var  = tot2 * (1.f / DMODEL) - mean * mean;
    const float rstd = rsqrtf(var + 1e-6f);

    float4 g4 = *(const float4*)&gamma[tid * 4];
    float4 b4 = *(const float4*)&beta[tid * 4];
    float4 o;
    o.x = (v.x - mean) * rstd * g4.x + b4.x;
    o.y = (v.y - mean) * rstd * g4.y + b4.y;
    o.z = (v.z - mean) * rstd * g4.z + b4.z;
    o.w = (v.w - mean) * rstd * g4.w + b4.w;
    *(float4*)&X[(size_t)row * DMODEL + tid * 4] = o;
}

// ---------------------------------------------------------------------------
// Launch
// ---------------------------------------------------------------------------
extern "C" void kernel_launch(void* const* d_in, const int* in_sizes, int n_in,
                              void* d_out, int out_size)
{
    (void)in_sizes; (void)n_in; (void)out_size;
    const float* q     = (const float*)d_in[0];
    const float* k     = (const float*)d_in[1];
    const float* v     = (const float*)d_in[2];
    const float* Wq    = (const float*)d_in[3];
    const float* bq    = (const float*)d_in[4];
    const float* Wk    = (const float*)d_in[5];
    const float* bk    = (const float*)d_in[6];
    const float* Wv    = (const float*)d_in[7];
    const float* bv    = (const float*)d_in[8];
    const float* Wo    = (const float*)d_in[9];
    const float* bo    = (const float*)d_in[10];
    const float* gamma = (const float*)d_in[11];
    const float* beta  = (const float*)d_in[12];
    float* out = (float*)d_out;

    __nv_bfloat16 *qp, *kp, *vp, *ctx, *qin, *kin, *vin, *wq, *wk, *wv, *wo;
    cudaGetSymbolAddress((void**)&qp,  g_qp);
    cudaGetSymbolAddress((void**)&kp,  g_kp);
    cudaGetSymbolAddress((void**)&vp,  g_vp);
    cudaGetSymbolAddress((void**)&ctx, g_ctx);
    cudaGetSymbolAddress((void**)&qin, g_qin);
    cudaGetSymbolAddress((void**)&kin, g_kin);
    cudaGetSymbolAddress((void**)&vin, g_vin);
    cudaGetSymbolAddress((void**)&wq,  g_wq);
    cudaGetSymbolAddress((void**)&wk,  g_wk);
    cudaGetSymbolAddress((void**)&wv,  g_wv);
    cudaGetSymbolAddress((void**)&wo,  g_wo);

    static int smem_set = 0;
    const int attn_smem = (128 * 72 + 4 * 64 * 72) * 2;
    if (!smem_set) {
        cudaFuncSetAttribute(attn_bf16, cudaFuncAttributeMaxDynamicSharedMemorySize, attn_smem);
        smem_set = 1;
    }

    // One-time conversions (graph-capturable, plain kernels)
    dim3 gCvtIn(MTOK * DMODEL / 4 / 256, 3);    // (8192, 3)
    cvt_inputs<<<gCvtIn, 256>>>(q, k, v, qin, kin, vin);
    dim3 gCvtW(DMODEL * DMODEL / 4 / 256, 4);   // (1024, 4)
    cvt_weights<<<gCvtW, 256>>>(Wq, Wk, Wv, Wo, wq, wk, wv, wo);

    dim3 gQKV(DMODEL / 128, MTOK / 128, 3);     // (8, 64, 3)
    gemm_qkv_bf16<<<gQKV, 256>>>(qin, kin, vin, wq, wk, wv, bq, bk, bv, qp, kp, vp);

    dim3 gAttn(SEQ / 128, BHEADS);              // (16, 64)
    attn_bf16<<<gAttn, 256, attn_smem>>>(qp, kp, vp, ctx);

    dim3 gGemm(DMODEL / 128, MTOK / 128);       // (8, 64)
    gemm_o_bf16<<<gGemm, 256>>>(ctx, wo, bo, q, out);

    layernorm_kernel<<<MTOK, 256>>>(out, gamma, beta);
}

// round 16
// speedup vs baseline: 14.5269x; 1.0604x over previous
#include <cuda_runtime.h>
#include <cuda_bf16.h>
#include <math.h>
#include <stdint.h>

// B=4, S=2048, D=1024, H=16, DK=64 -> M = 8192 tokens.
// Head split reshape(B*H, S, DK) is an identity on the flat buffer.
#define MTOK   8192
#define DMODEL 1024
#define BHEADS 64
#define SEQ    2048
#define DKH    64

// Scratch (device globals; bf16 rounding equals the cvt consumers did anyway)
__device__ __nv_bfloat16 g_qp [MTOK * DMODEL];
__device__ __nv_bfloat16 g_kp [MTOK * DMODEL];
__device__ __nv_bfloat16 g_vp [MTOK * DMODEL];
__device__ __nv_bfloat16 g_ctx[MTOK * DMODEL];
// Pre-converted bf16 inputs and weights
__device__ __nv_bfloat16 g_qin[MTOK * DMODEL];
__device__ __nv_bfloat16 g_kin[MTOK * DMODEL];
__device__ __nv_bfloat16 g_vin[MTOK * DMODEL];
__device__ __nv_bfloat16 g_wq [DMODEL * DMODEL];
__device__ __nv_bfloat16 g_wk [DMODEL * DMODEL];
__device__ __nv_bfloat16 g_wv [DMODEL * DMODEL];
__device__ __nv_bfloat16 g_wo [DMODEL * DMODEL];

// Q pre-scale: 1/sqrt(64) * log2(e)  -> scores land in the exp2 domain.
#define QSCALE 0.18033688011112042f

// ---------------------------------------------------------------------------
// PTX helpers
// ---------------------------------------------------------------------------
__device__ __forceinline__ uint32_t packbf(float lo, float hi) {
    uint32_t r;
    asm("cvt.rn.bf16x2.f32 %0, %1, %2;" : "=r"(r) : "f"(hi), "f"(lo));
    return r;
}

__device__ __forceinline__ float ex2(float x) {
    float r;
    asm("ex2.approx.f32 %0, %1;" : "=f"(r) : "f"(x));
    return r;
}

__device__ __forceinline__ void ldsm4(uint32_t* r, uint32_t saddr) {
    asm volatile("ldmatrix.sync.aligned.m8n8.x4.shared.b16 {%0,%1,%2,%3}, [%4];"
                 : "=r"(r[0]), "=r"(r[1]), "=r"(r[2]), "=r"(r[3]) : "r"(saddr));
}

__device__ __forceinline__ void ldsm4t(uint32_t* r, uint32_t saddr) {
    asm volatile("ldmatrix.sync.aligned.m8n8.x4.trans.shared.b16 {%0,%1,%2,%3}, [%4];"
                 : "=r"(r[0]), "=r"(r[1]), "=r"(r[2]), "=r"(r[3]) : "r"(saddr));
}

__device__ __forceinline__ void mma_bf16(float* c, const uint32_t* a, const uint32_t* b) {
    asm volatile(
        "mma.sync.aligned.m16n8k16.row.col.f32.bf16.bf16.f32 "
        "{%0,%1,%2,%3}, {%4,%5,%6,%7}, {%8,%9}, {%0,%1,%2,%3};"
        : "+f"(c[0]), "+f"(c[1]), "+f"(c[2]), "+f"(c[3])
        : "r"(a[0]), "r"(a[1]), "r"(a[2]), "r"(a[3]), "r"(b[0]), "r"(b[1]));
}

__device__ __forceinline__ void cpasync16(uint32_t smem, const void* gmem) {
    asm volatile("cp.async.cg.shared.global [%0], [%1], 16;" :: "r"(smem), "l"(gmem));
}
#define CP_COMMIT() asm volatile("cp.async.commit_group;")
#define CP_WAIT(N)  asm volatile("cp.async.wait_group %0;" :: "n"(N))

// ---------------------------------------------------------------------------
// fp32 -> bf16 conversion kernels (one-time per launch)
// ---------------------------------------------------------------------------
__global__ __launch_bounds__(256)
void cvt_inputs(const float* __restrict__ a, const float* __restrict__ b,
                const float* __restrict__ c,
                __nv_bfloat16* __restrict__ oa, __nv_bfloat16* __restrict__ ob,
                __nv_bfloat16* __restrict__ oc)
{
    const float* in; __nv_bfloat16* out;
    if (blockIdx.y == 0)      { in = a; out = oa; }
    else if (blockIdx.y == 1) { in = b; out = ob; }
    else                      { in = c; out = oc; }
    const size_t i = ((size_t)blockIdx.x * 256 + threadIdx.x) * 4;
    float4 v = *(const float4*)&in[i];
    uint2 u; u.x = packbf(v.x, v.y); u.y = packbf(v.z, v.w);
    *(uint2*)&out[i] = u;
}

__global__ __launch_bounds__(256)
void cvt_weights(const float* __restrict__ a, const float* __restrict__ b,
                 const float* __restrict__ c, const float* __restrict__ d,
                 __nv_bfloat16* __restrict__ oa, __nv_bfloat16* __restrict__ ob,
                 __nv_bfloat16* __restrict__ oc, __nv_bfloat16* __restrict__ od)
{
    const float* in; __nv_bfloat16* out;
    if (blockIdx.y == 0)      { in = a; out = oa; }
    else if (blockIdx.y == 1) { in = b; out = ob; }
    else if (blockIdx.y == 2) { in = c; out = oc; }
    else                      { in = d; out = od; }
    const size_t i = ((size_t)blockIdx.x * 256 + threadIdx.x) * 4;
    float4 v = *(const float4*)&in[i];
    uint2 u; u.x = packbf(v.x, v.y); u.y = packbf(v.z, v.w);
    *(uint2*)&out[i] = u;
}

// ---------------------------------------------------------------------------
// All-bf16 GEMM body, cp.async 2-stage ring with ONE barrier per stage
// (wait -> sync -> prefetch s+1 -> compute s). Block 128x128, BK=32, 8 warps.
// oscale multiplies (acc + bias) before output (used for Q pre-scaling).
// ---------------------------------------------------------------------------
template<bool RES, bool CBF>
__device__ __forceinline__
void gemm_body(const __nv_bfloat16* __restrict__ X, const __nv_bfloat16* __restrict__ W,
               const float* __restrict__ bias, const float* __restrict__ R,
               void* __restrict__ Cv, int m0, int n0, float oscale)
{
    __shared__ __nv_bfloat16 Xs[2][128 * 40];
    __shared__ __nv_bfloat16 Ws[2][128 * 40];

    const int tid  = threadIdx.x;
    const int lane = tid & 31;
    const int wid  = tid >> 5;
    const int wm   = (wid & 1) * 64;
    const int wn   = (wid >> 1) * 32;

    float acc[4][4][4];
#pragma unroll
    for (int i = 0; i < 4; i++)
#pragma unroll
        for (int j = 0; j < 4; j++)
#pragma unroll
            for (int c = 0; c < 4; c++) acc[i][j][c] = 0.f;

    const uint32_t xs0 = (uint32_t)__cvta_generic_to_shared(&Xs[0][0]);
    const uint32_t ws0 = (uint32_t)__cvta_generic_to_shared(&Ws[0][0]);

    const int c_row = tid >> 2;          // +64 for second chunk
    const int c_col = (tid & 3) * 16;

    auto stage = [&](int K0, int buf) {
        const uint32_t xb = xs0 + (uint32_t)(buf * 128 * 80);
        const uint32_t wb = ws0 + (uint32_t)(buf * 128 * 80);
#pragma unroll
        for (int it = 0; it < 2; it++) {
            const int row = c_row + it * 64;
            cpasync16(xb + (uint32_t)(row * 80 + c_col),
                      (const char*)&X[(size_t)(m0 + row) * DMODEL + K0] + c_col);
            cpasync16(wb + (uint32_t)(row * 80 + c_col),
                      (const char*)&W[(size_t)(n0 + row) * DMODEL + K0] + c_col);
        }
    };

    const int a_row = wm + (lane & 15);
    const int a_byt = 16 * (lane >> 4);
    const int b_row = wn + 8 * (lane >> 4) + (lane & 7);
    const int b_byt = 16 * ((lane >> 3) & 1);

    stage(0, 0);
    CP_COMMIT();

    const int NS = DMODEL / 32;   // 32 stages
    for (int s = 0; s < NS; s++) {
        const int buf = s & 1;
        CP_WAIT(0);
        __syncthreads();
        if (s + 1 < NS) {                 // prefetch overlaps compute of s
            stage((s + 1) * 32, buf ^ 1);
            CP_COMMIT();
        }

        const uint32_t xb = xs0 + (uint32_t)(buf * 128 * 80);
        const uint32_t wb = ws0 + (uint32_t)(buf * 128 * 80);
#pragma unroll
        for (int kk = 0; kk < 32; kk += 16) {
            uint32_t A[4][4], Bf[2][4];
#pragma unroll
            for (int i = 0; i < 4; i++)
                ldsm4(A[i], xb + (uint32_t)((a_row + 16 * i) * 80 + 2 * kk + a_byt));
#pragma unroll
            for (int tp = 0; tp < 2; tp++)
                ldsm4(Bf[tp], wb + (uint32_t)((b_row + 16 * tp) * 80 + 2 * kk + b_byt));
#pragma unroll
            for (int i = 0; i < 4; i++)
#pragma unroll
                for (int j = 0; j < 4; j++)
                    mma_bf16(acc[i][j], A[i], &Bf[j >> 1][(j & 1) * 2]);
        }
    }

    // Epilogue
    const int q = lane & 3, g = lane >> 2;
#pragma unroll
    for (int i = 0; i < 4; i++) {
#pragma unroll
        for (int j = 0; j < 4; j++) {
            const int row0 = m0 + wm + 16 * i + g;
            const int col  = n0 + wn + 8 * j + 2 * q;
            float2 bi = *(const float2*)&bias[col];
            float a0 = (acc[i][j][0] + bi.x) * oscale, a1 = (acc[i][j][1] + bi.y) * oscale;
            float a2 = (acc[i][j][2] + bi.x) * oscale, a3 = (acc[i][j][3] + bi.y) * oscale;
            if (RES) {
                float2 r0 = *(const float2*)&R[(size_t)row0 * DMODEL + col];
                float2 r1 = *(const float2*)&R[(size_t)(row0 + 8) * DMODEL + col];
                a0 += r0.x; a1 += r0.y; a2 += r1.x; a3 += r1.y;
            }
            if (CBF) {
                __nv_bfloat16* Cb = (__nv_bfloat16*)Cv;
                *(uint32_t*)&Cb[(size_t)row0 * DMODEL + col]       = packbf(a0, a1);
                *(uint32_t*)&Cb[(size_t)(row0 + 8) * DMODEL + col] = packbf(a2, a3);
            } else {
                float* Cf = (float*)Cv;
                float2 o0; o0.x = a0; o0.y = a1;
                float2 o1; o1.x = a2; o1.y = a3;
                *(float2*)&Cf[(size_t)row0 * DMODEL + col]       = o0;
                *(float2*)&Cf[(size_t)(row0 + 8) * DMODEL + col] = o1;
            }
        }
    }
}

// Batched QKV projection; Q output pre-scaled by QSCALE.
__global__ __launch_bounds__(256, 2)
void gemm_qkv_bf16(const __nv_bfloat16* __restrict__ xq, const __nv_bfloat16* __restrict__ xk,
                   const __nv_bfloat16* __restrict__ xv,
                   const __nv_bfloat16* __restrict__ Wq, const __nv_bfloat16* __restrict__ Wk,
                   const __nv_bfloat16* __restrict__ Wv,
                   const float* __restrict__ bq, const float* __restrict__ bk,
                   const float* __restrict__ bv,
                   __nv_bfloat16* __restrict__ qp, __nv_bfloat16* __restrict__ kp,
                   __nv_bfloat16* __restrict__ vp)
{
    const __nv_bfloat16 *X, *W;
    const float* b;
    __nv_bfloat16* C;
    float sc;
    if (blockIdx.z == 0)      { X = xq; W = Wq; b = bq; C = qp; sc = QSCALE; }
    else if (blockIdx.z == 1) { X = xk; W = Wk; b = bk; C = kp; sc = 1.f; }
    else                      { X = xv; W = Wv; b = bv; C = vp; sc = 1.f; }
    gemm_body<false, true>(X, W, b, nullptr, C, blockIdx.y * 128, blockIdx.x * 128, sc);
}

// O projection (bf16 in -> fp32 out) with fp32 residual add.
__global__ __launch_bounds__(256, 2)
void gemm_o_bf16(const __nv_bfloat16* __restrict__ X, const __nv_bfloat16* __restrict__ W,
                 const float* __restrict__ bias, const float* __restrict__ R,
                 float* __restrict__ C)
{
    gemm_body<true, false>(X, W, bias, R, C, blockIdx.y * 128, blockIdx.x * 128, 1.f);
}

// ---------------------------------------------------------------------------
// BF16 flash attention; 3-stage cp.async K/V ring, ONE barrier per key tile.
// Q is pre-scaled by 1/8*log2e, so softmax uses bare ex2.
// Block: q-tile 128, key tiles of 64, 8 warps (16 q rows each).
// ---------------------------------------------------------------------------
__global__ __launch_bounds__(256)
void attn_bf16(const __nv_bfloat16* __restrict__ Qp,
               const __nv_bfloat16* __restrict__ Kp,
               const __nv_bfloat16* __restrict__ Vp,
               __nv_bfloat16* __restrict__ Ctx)
{
    extern __shared__ __nv_bfloat16 smdyn[];
    __nv_bfloat16* Qs = smdyn;               // 128*72
    __nv_bfloat16* Ks = Qs + 128 * 72;       // 3 stages * 64*72
    __nv_bfloat16* Vs = Ks + 3 * 64 * 72;    // 3 stages * 64*72

    const int tid  = threadIdx.x;
    const int lane = tid & 31;
    const int wid  = tid >> 5;
    const int bh   = blockIdx.y;
    const int q0   = blockIdx.x * 128;
    const size_t base = (size_t)bh * SEQ * DKH;

    const int q = lane & 3, g = lane >> 2;

    const int a_row = 16 * wid + (lane & 15);
    const int a_byt = 16 * (lane >> 4);
    const int k_row = 8 * (lane >> 4) + (lane & 7);
    const int k_byt = 16 * ((lane >> 3) & 1);
    const int v_row = 8 * ((lane >> 3) & 1) + (lane & 7);
    const int v_byt = 16 * (lane >> 4);

    const uint32_t qs_b = (uint32_t)__cvta_generic_to_shared(Qs);
    const uint32_t ks_b = (uint32_t)__cvta_generic_to_shared(Ks);
    const uint32_t vs_b = (uint32_t)__cvta_generic_to_shared(Vs);

    const int c_row0 = tid >> 3;
    const int c_col0 = (tid & 7) * 16;

    auto stage_kv = [&](int kt, int buf) {
        const __nv_bfloat16* Kg = Kp + base + (size_t)(kt * 64) * DKH;
        const __nv_bfloat16* Vg = Vp + base + (size_t)(kt * 64) * DKH;
        const uint32_t kb = ks_b + (uint32_t)(buf * 64 * 144);
        const uint32_t vb = vs_b + (uint32_t)(buf * 64 * 144);
#pragma unroll
        for (int it = 0; it < 2; it++) {
            const int row = c_row0 + it * 32;
            cpasync16(kb + (uint32_t)(row * 144 + c_col0),
                      (const char*)Kg + (size_t)row * 128 + c_col0);
            cpasync16(vb + (uint32_t)(row * 144 + c_col0),
                      (const char*)Vg + (size_t)row * 128 + c_col0);
        }
    };

    // Prologue: Q + KV0 (group 0), KV1 (group 1)
    {
        const __nv_bfloat16* Qg = Qp + base + (size_t)q0 * DKH;
#pragma unroll
        for (int it = 0; it < 4; it++) {
            const int row = c_row0 + it * 32;
            cpasync16(qs_b + (uint32_t)(row * 144 + c_col0),
                      (const char*)Qg + (size_t)row * 128 + c_col0);
        }
        stage_kv(0, 0);
        CP_COMMIT();
        stage_kv(1, 1);
        CP_COMMIT();
    }

    float m0r = -INFINITY, m1r = -INFINITY, l0 = 0.f, l1 = 0.f;
    float o[8][4];
#pragma unroll
    for (int j = 0; j < 8; j++)
#pragma unroll
        for (int c = 0; c < 4; c++) o[j][c] = 0.f;

    const int NT = SEQ / 64;   // 32
    for (int kt = 0; kt < NT; kt++) {
        const int cur = kt % 3;
        if (kt + 1 < NT) { CP_WAIT(1); } else { CP_WAIT(0); }
        __syncthreads();                      // all warps done with buf (kt-1)%3
        if (kt + 2 < NT) {                    // prefetch overlaps compute of kt
            stage_kv(kt + 2, (kt + 2) % 3);
            CP_COMMIT();
        }

        const uint32_t kcur = ks_b + (uint32_t)(cur * 64 * 144);
        const uint32_t vcur = vs_b + (uint32_t)(cur * 64 * 144);

        // --- Scores (already in exp2 domain thanks to Q pre-scale) ---
        float s[8][4];
#pragma unroll
        for (int j = 0; j < 8; j++)
#pragma unroll
            for (int c = 0; c < 4; c++) s[j][c] = 0.f;

#pragma unroll
        for (int kk = 0; kk < 64; kk += 16) {
            uint32_t A[4], Bf[4][4];
            ldsm4(A, qs_b + (uint32_t)(a_row * 144 + 2 * kk + a_byt));
#pragma unroll
            for (int tp = 0; tp < 4; tp++)
                ldsm4(Bf[tp], kcur + (uint32_t)((k_row + 16 * tp) * 144 + 2 * kk + k_byt));
#pragma unroll
            for (int j = 0; j < 8; j++)
                mma_bf16(s[j], A, &Bf[j >> 1][(j & 1) * 2]);
        }

        // --- Online softmax with ex2 ---
        float mx0 = s[0][0], mx1 = s[0][2];
#pragma unroll
        for (int j = 0; j < 8; j++) {
            mx0 = fmaxf(mx0, fmaxf(s[j][0], s[j][1]));
            mx1 = fmaxf(mx1, fmaxf(s[j][2], s[j][3]));
        }
        mx0 = fmaxf(mx0, __shfl_xor_sync(0xffffffffu, mx0, 1));
        mx0 = fmaxf(mx0, __shfl_xor_sync(0xffffffffu, mx0, 2));
        mx1 = fmaxf(mx1, __shfl_xor_sync(0xffffffffu, mx1, 1));
        mx1 = fmaxf(mx1, __shfl_xor_sync(0xffffffffu, mx1, 2));
        const float mn0 = fmaxf(m0r, mx0), mn1 = fmaxf(m1r, mx1);
        const float al0 = ex2(m0r - mn0), al1 = ex2(m1r - mn1);

        float sum0 = 0.f, sum1 = 0.f;
#pragma unroll
        for (int j = 0; j < 8; j++) {
            s[j][0] = ex2(s[j][0] - mn0);
            s[j][1] = ex2(s[j][1] - mn0);
            s[j][2] = ex2(s[j][2] - mn1);
            s[j][3] = ex2(s[j][3] - mn1);
            sum0 += s[j][0] + s[j][1];
            sum1 += s[j][2] + s[j][3];
        }
        sum0 += __shfl_xor_sync(0xffffffffu, sum0, 1);
        sum0 += __shfl_xor_sync(0xffffffffu, sum0, 2);
        sum1 += __shfl_xor_sync(0xffffffffu, sum1, 1);
        sum1 += __shfl_xor_sync(0xffffffffu, sum1, 2);
        l0 = l0 * al0 + sum0;
        l1 = l1 * al1 + sum1;
        m0r = mn0; m1r = mn1;

#pragma unroll
        for (int j = 0; j < 8; j++) {
            o[j][0] *= al0; o[j][1] *= al0;
            o[j][2] *= al1; o[j][3] *= al1;
        }

        // --- Pack P accumulator fragments into PV A fragments (registers) ---
        uint32_t pA[4][4];
#pragma unroll
        for (int kc = 0; kc < 4; kc++) {
            pA[kc][0] = packbf(s[2 * kc][0],     s[2 * kc][1]);
            pA[kc][1] = packbf(s[2 * kc][2],     s[2 * kc][3]);
            pA[kc][2] = packbf(s[2 * kc + 1][0], s[2 * kc + 1][1]);
            pA[kc][3] = packbf(s[2 * kc + 1][2], s[2 * kc + 1][3]);
        }

        // --- ctx += P · V ---
#pragma unroll
        for (int kc = 0; kc < 4; kc++) {
#pragma unroll
            for (int jp = 0; jp < 4; jp++) {
                uint32_t Vf[4];
                ldsm4t(Vf, vcur + (uint32_t)((16 * kc + v_row) * 144 + 32 * jp + v_byt));
                mma_bf16(o[2 * jp],     pA[kc], &Vf[0]);
                mma_bf16(o[2 * jp + 1], pA[kc], &Vf[2]);
            }
        }
    }

    const float inv0 = 1.f / l0, inv1 = 1.f / l1;
    const int row0 = q0 + 16 * wid + g;
#pragma unroll
    for (int j = 0; j < 8; j++) {
        uint32_t u0 = packbf(o[j][0] * inv0, o[j][1] * inv0);
        uint32_t u1 = packbf(o[j][2] * inv1, o[j][3] * inv1);
        *(uint32_t*)&Ctx[base + (size_t)row0 * DKH + 8 * j + 2 * q]       = u0;
        *(uint32_t*)&Ctx[base + (size_t)(row0 + 8) * DKH + 8 * j + 2 * q] = u1;
    }
}

// ---------------------------------------------------------------------------
// In-place LayerNorm over last dim (1024). One block (256 thr) per row.
// ---------------------------------------------------------------------------
__global__ __launch_bounds__(256)
void layernorm_kernel(float* __restrict__ X, const float* __restrict__ gamma,
                      const float* __restrict__ beta)
{
    __shared__ float rs[8], rss[8];
    const int row = blockIdx.x;
    const int tid = threadIdx.x;

    float4 v = *(const float4*)&X[(size_t)row * DMODEL + tid * 4];
    float s  = v.x + v.y + v.z + v.w;
    float ss = v.x * v.x + v.y * v.y + v.z * v.z + v.w * v.w;

#pragma unroll
    for (int o = 16; o > 0; o >>= 1) {
        s  += __shfl_down_sync(0xffffffffu, s,  o);
        ss += __shfl_down_sync(0xffffffffu, ss, o);
    }
    const int w  = tid >> 5;
    const int ln = tid & 31;
    if (ln == 0) { rs[w] = s; rss[w] = ss; }
    __syncthreads();

    float tot = 0.f, tot2 = 0.f;
#pragma unroll
    for (int i = 0; i < 8; i++) { tot += rs[i]; tot2 += rss[i]; }
    const float mean = tot * (1.f / DMODEL);
    const float var  = tot2 * (1.f / DMODEL) - mean * mean;
    const float rstd = rsqrtf(var + 1e-6f);

    float4 g4 = *(const float4*)&gamma[tid * 4];
    float4 b4 = *(const float4*)&beta[tid * 4];
    float4 o;
    o.x = (v.x - mean) * rstd * g4.x + b4.x;
    o.y = (v.y - mean) * rstd * g4.y + b4.y;
    o.z = (v.z - mean) * rstd * g4.z + b4.z;
    o.w = (v.w - mean) * rstd * g4.w + b4.w;
    *(float4*)&X[(size_t)row * DMODEL + tid * 4] = o;
}

// ---------------------------------------------------------------------------
// Launch
// ---------------------------------------------------------------------------
extern "C" void kernel_launch(void* const* d_in, const int* in_sizes, int n_in,
                              void* d_out, int out_size)
{
    (void)in_sizes; (void)n_in; (void)out_size;
    const float* q     = (const float*)d_in[0];
    const float* k     = (const float*)d_in[1];
    const float* v     = (const float*)d_in[2];
    const float* Wq    = (const float*)d_in[3];
    const float* bq    = (const float*)d_in[4];
    const float* Wk    = (const float*)d_in[5];
    const float* bk    = (const float*)d_in[6];
    const float* Wv    = (const float*)d_in[7];
    const float* bv    = (const float*)d_in[8];
    const float* Wo    = (const float*)d_in[9];
    const float* bo    = (const float*)d_in[10];
    const float* gamma = (const float*)d_in[11];
    const float* beta  = (const float*)d_in[12];
    float* out = (float*)d_out;

    __nv_bfloat16 *qp, *kp, *vp, *ctx, *qin, *kin, *vin, *wq, *wk, *wv, *wo;
    cudaGetSymbolAddress((void**)&qp,  g_qp);
    cudaGetSymbolAddress((void**)&kp,  g_kp);
    cudaGetSymbolAddress((void**)&vp,  g_vp);
    cudaGetSymbolAddress((void**)&ctx, g_ctx);
    cudaGetSymbolAddress((void**)&qin, g_qin);
    cudaGetSymbolAddress((void**)&kin, g_kin);
    cudaGetSymbolAddress((void**)&vin, g_vin);
    cudaGetSymbolAddress((void**)&wq,  g_wq);
    cudaGetSymbolAddress((void**)&wk,  g_wk);
    cudaGetSymbolAddress((void**)&wv,  g_wv);
    cudaGetSymbolAddress((void**)&wo,  g_wo);

    static int smem_set = 0;
    const int attn_smem = (128 * 72 + 6 * 64 * 72) * 2;   // Q + 3*(K+V)
    if (!smem_set) {
        cudaFuncSetAttribute(attn_bf16, cudaFuncAttributeMaxDynamicSharedMemorySize, attn_smem);
        smem_set = 1;
    }

    dim3 gCvtIn(MTOK * DMODEL / 4 / 256, 3);    // (8192, 3)
    cvt_inputs<<<gCvtIn, 256>>>(q, k, v, qin, kin, vin);
    dim3 gCvtW(DMODEL * DMODEL / 4 / 256, 4);   // (1024, 4)
    cvt_weights<<<gCvtW, 256>>>(Wq, Wk, Wv, Wo, wq, wk, wv, wo);

    dim3 gQKV(DMODEL / 128, MTOK / 128, 3);     // (8, 64, 3)
    gemm_qkv_bf16<<<gQKV, 256>>>(qin, kin, vin, wq, wk, wv, bq, bk, bv, qp, kp, vp);

    dim3 gAttn(SEQ / 128, BHEADS);              // (16, 64)
    attn_bf16<<<gAttn, 256, attn_smem>>>(qp, kp, vp, ctx);

    dim3 gGemm(DMODEL / 128, MTOK / 128);       // (8, 64)
    gemm_o_bf16<<<gGemm, 256>>>(ctx, wo, bo, q, out);

    layernorm_kernel<<<MTOK, 256>>>(out, gamma, beta);
}